// round 10
// baseline (speedup 1.0000x reference)
#include <cuda_runtime.h>
#include <cuda_bf16.h>
#include <math.h>

#define C   64
#define HW  64
#define NSP 4096          // N = HW*HW spatial positions
#define BB  8             // batch
#define EPSBN 1e-5f

// attention tiling
#define TNQ 256           // query rows per CTA (8 warps x 32 rows)
#define TMK 64            // key/value chunk
#define PK64 68           // K smem pitch (u64): [16 slots][64 j]
#define PV64 20           // V smem pitch (u64): [64 d][16 slots]

// scale: (1/8) * log2(e)  -> logits in log2 domain, exp == exp2
#define QSCALE 0.18033688f

// scratch (no allocations allowed -> device globals)
__device__ unsigned long long g_K64[BB * 16 * NSP];
__device__ unsigned long long g_V64[BB * 64 * 64 * 16];
__device__ float g_attn[BB * C * NSP];       // attention output

// ---------------------------------------------------------------------------
// helpers
// ---------------------------------------------------------------------------
__device__ __forceinline__ unsigned packbf16(float lo, float hi) {
    unsigned r;
    asm("cvt.rn.bf16x2.f32 %0, %1, %2;" : "=r"(r) : "f"(hi), "f"(lo));
    return r;
}

__device__ __forceinline__ float ex2(float x) {
    float r;
    asm("ex2.approx.ftz.f32 %0, %1;" : "=f"(r) : "f"(x));
    return r;
}

__device__ __forceinline__ void mma_bf16(float c[4],
                                         unsigned a0, unsigned a1, unsigned a2, unsigned a3,
                                         unsigned b0, unsigned b1) {
    asm volatile(
        "mma.sync.aligned.m16n8k16.row.col.f32.bf16.bf16.f32 "
        "{%0,%1,%2,%3},{%4,%5,%6,%7},{%8,%9},{%0,%1,%2,%3};\n"
        : "+f"(c[0]), "+f"(c[1]), "+f"(c[2]), "+f"(c[3])
        : "r"(a0), "r"(a1), "r"(a2), "r"(a3), "r"(b0), "r"(b1));
}

__device__ __forceinline__ void cpa16(unsigned smem_addr, const void* gptr) {
    asm volatile("cp.async.cg.shared.global [%0], [%1], 16;"
                 :: "r"(smem_addr), "l"(gptr));
}

// ---------------------------------------------------------------------------
// conv1x1 (w1) + BN1 + ReLU -> g_V64 ; packs K = x into g_K64
// ---------------------------------------------------------------------------
__global__ __launch_bounds__(256) void conv1_kernel(
    const float* __restrict__ x, const float* __restrict__ w1,
    const float* __restrict__ g, const float* __restrict__ bb,
    const float* __restrict__ m, const float* __restrict__ v)
{
    __shared__ float ws[C * C];
    __shared__ float s_inv[C], s_shift[C];
    int tid = threadIdx.x;
    for (int i = tid; i < C * C; i += 256) ws[i] = w1[i];
    if (tid < C) {
        float inv = g[tid] * rsqrtf(v[tid] + EPSBN);
        s_inv[tid] = inv;
        s_shift[tid] = bb[tid] - m[tid] * inv;
    }
    __syncthreads();

    int h = tid >> 6;                 // output quarter 0..3
    int p = tid & 63;
    int b = blockIdx.y;
    int n = blockIdx.x * 64 + p;
    const float* xp = x + (size_t)b * C * NSP + n;
    float xv[C];
#pragma unroll
    for (int c = 0; c < C; c++) xv[c] = xp[(size_t)c * NSP];

    // ---- K packing (quarter 0 threads): 16 u64 slots per position ----
    if (h == 0) {
        unsigned long long* kp = g_K64 + (size_t)b * 16 * NSP + n;
#pragma unroll
        for (int s = 0; s < 16; s++) {
            int ks = s >> 2, q = s & 3;
            int dlo = ks * 8 + q, dhi = dlo + 4;
            unsigned lo = packbf16(xv[2 * dlo], xv[2 * dlo + 1]);
            unsigned hi = packbf16(xv[2 * dhi], xv[2 * dhi + 1]);
            kp[(size_t)s * NSP] = (unsigned long long)lo | ((unsigned long long)hi << 32);
        }
    }

    // ---- conv + BN + ReLU into registers (16 outputs) ----
    float vout[16];
    int o0 = h * 16;
#pragma unroll 4
    for (int oo = 0; oo < 16; oo++) {
        int o = o0 + oo;
        const float4* wr = (const float4*)(ws + o * C);
        float a0 = 0.f, a1 = 0.f, a2 = 0.f, a3 = 0.f;
#pragma unroll
        for (int k = 0; k < 16; k++) {
            float4 f = wr[k];
            a0 += f.x * xv[4 * k + 0];
            a1 += f.y * xv[4 * k + 1];
            a2 += f.z * xv[4 * k + 2];
            a3 += f.w * xv[4 * k + 3];
        }
        float acc = (a0 + a1) + (a2 + a3);
        vout[oo] = fmaxf(acc * s_inv[o] + s_shift[o], 0.f);
    }

    // ---- V packing: n-pairs via shuffle, write u32 half of u64 slot ----
    {
        bool evenl = !(n & 1);
        int np = n >> 1;
        int ch = n >> 6;
        int jp = np & 31;
        int qq = jp & 7, jt = jp >> 3;
        int t = (qq < 4) ? (jt * 4 + qq) : (jt * 4 + qq - 4);
        int half = (qq < 4) ? 0 : 1;
        unsigned* vp32 = (unsigned*)g_V64;
#pragma unroll
        for (int oo = 0; oo < 16; oo++) {
            float other = __shfl_down_sync(0xffffffffu, vout[oo], 1);
            if (evenl) {
                int d = o0 + oo;
                size_t idx = ((((size_t)b * 64 + d) * 64 + ch) * 16 + t) * 2 + half;
                vp32[idx] = packbf16(vout[oo], other);
            }
        }
    }
}

// ---------------------------------------------------------------------------
// flash attention, bf16 m16n8k16, no-max softmax, Q in regs,
// K/V double-buffered cp.async; exp/pack fused into PV loop for pipe overlap.
// ---------------------------------------------------------------------------
__global__ __launch_bounds__(256) void attn_mma_kernel(const float* __restrict__ x)
{
    __shared__ __align__(16) unsigned long long Ks64[2][16 * PK64];
    __shared__ __align__(16) unsigned long long Vs64[2][64 * PV64];

    const int tid  = threadIdx.x;
    const int lane = tid & 31;
    const int wid  = tid >> 5;
    const int g    = lane >> 2;       // 0..7
    const int q    = lane & 3;        // 0..3
    const int i0   = wid * 32;

    const int b  = blockIdx.y;
    const int n0 = blockIdx.x * TNQ;
    const float* xb = x + (size_t)b * C * NSP;
    const unsigned long long* kb64 = g_K64 + (size_t)b * 16 * NSP;
    const unsigned long long* vb64 = g_V64 + (size_t)b * 64 * 64 * 16;

    unsigned ksa[2], vsa[2];
    ksa[0] = (unsigned)__cvta_generic_to_shared(&Ks64[0][0]);
    ksa[1] = (unsigned)__cvta_generic_to_shared(&Ks64[1][0]);
    vsa[0] = (unsigned)__cvta_generic_to_shared(&Vs64[0][0]);
    vsa[1] = (unsigned)__cvta_generic_to_shared(&Vs64[1][0]);
    const int i2  = tid * 2;
    const int i2b = i2 + 512;

    // ---- Q A-fragments straight into registers (scale folded) ----
    unsigned QA[4][2][4];
#pragma unroll
    for (int ks = 0; ks < 4; ks++) {
#pragma unroll
        for (int rb = 0; rb < 2; rb++) {
            int re = n0 + i0 + rb * 16 + g;
            int d0 = 16 * ks + 2 * q;
            QA[ks][rb][0] = packbf16(xb[(size_t)d0 * NSP + re] * QSCALE,
                                     xb[(size_t)(d0 + 1) * NSP + re] * QSCALE);
            QA[ks][rb][1] = packbf16(xb[(size_t)d0 * NSP + re + 8] * QSCALE,
                                     xb[(size_t)(d0 + 1) * NSP + re + 8] * QSCALE);
            QA[ks][rb][2] = packbf16(xb[(size_t)(d0 + 8) * NSP + re] * QSCALE,
                                     xb[(size_t)(d0 + 9) * NSP + re] * QSCALE);
            QA[ks][rb][3] = packbf16(xb[(size_t)(d0 + 8) * NSP + re + 8] * QSCALE,
                                     xb[(size_t)(d0 + 9) * NSP + re + 8] * QSCALE);
        }
    }

    float SC[2][8][4];
    float OC[2][8][4];
#pragma unroll
    for (int rb = 0; rb < 2; rb++)
#pragma unroll
        for (int t = 0; t < 8; t++)
            OC[rb][t][0] = OC[rb][t][1] = OC[rb][t][2] = OC[rb][t][3] = 0.f;
    float rl[2][2] = {{0.f, 0.f}, {0.f, 0.f}};

    #define ISSUE_CHUNK(m0, buf) do {                                                   \
        int _ch = (m0) >> 6;                                                            \
        cpa16(ksa[buf] + ((i2  >> 6) * PK64 + (i2  & 63)) * 8,                          \
              kb64 + (size_t)(i2  >> 6) * NSP + (m0) + (i2  & 63));                     \
        cpa16(ksa[buf] + ((i2b >> 6) * PK64 + (i2b & 63)) * 8,                          \
              kb64 + (size_t)(i2b >> 6) * NSP + (m0) + (i2b & 63));                     \
        cpa16(vsa[buf] + ((i2  >> 4) * PV64 + (i2  & 15)) * 8,                          \
              vb64 + (size_t)((i2  >> 4) * 64 + _ch) * 16 + (i2  & 15));                \
        cpa16(vsa[buf] + ((i2b >> 4) * PV64 + (i2b & 15)) * 8,                          \
              vb64 + (size_t)((i2b >> 4) * 64 + _ch) * 16 + (i2b & 15));                \
        asm volatile("cp.async.commit_group;");                                         \
    } while (0)

    ISSUE_CHUNK(0, 0);

    for (int mm = 0; mm < NSP / TMK; mm++) {
        int cur = mm & 1;
        __syncthreads();              // compute(mm-1) done -> buf (1-cur) free
        if (mm + 1 < NSP / TMK) {
            ISSUE_CHUNK((mm + 1) * TMK, 1 - cur);
            asm volatile("cp.async.wait_group 1;");
        } else {
            asm volatile("cp.async.wait_group 0;");
        }
        asm volatile("bar.sync 1, 256;" ::: "memory");   // chunk mm visible to all

        const uint2* Kc = (const uint2*)&Ks64[cur][0];
        const uint2* Vc = (const uint2*)&Vs64[cur][0];

        // ---- S = Q K^T ----
#pragma unroll
        for (int rb = 0; rb < 2; rb++)
#pragma unroll
            for (int t = 0; t < 8; t++)
                SC[rb][t][0] = SC[rb][t][1] = SC[rb][t][2] = SC[rb][t][3] = 0.f;
#pragma unroll
        for (int ks = 0; ks < 4; ks++) {
            int srow = (ks * 4 + q) * PK64;
#pragma unroll
            for (int nt = 0; nt < 8; nt++) {
                uint2 kf = Kc[srow + nt * 8 + g];
                mma_bf16(SC[0][nt], QA[ks][0][0], QA[ks][0][1], QA[ks][0][2], QA[ks][0][3], kf.x, kf.y);
                mma_bf16(SC[1][nt], QA[ks][1][0], QA[ks][1][1], QA[ks][1][2], QA[ks][1][3], kf.x, kf.y);
            }
        }

        // ---- fused: per jt step, exp+pack the 2 needed S tiles, then PV mma ----
#pragma unroll
        for (int jt = 0; jt < 4; jt++) {
            unsigned aA0, aA1, aA2, aA3, aB0, aB1, aB2, aB3;
            {
                float e0 = ex2(SC[0][2 * jt][0]),     e1 = ex2(SC[0][2 * jt][1]);
                float e2 = ex2(SC[0][2 * jt][2]),     e3 = ex2(SC[0][2 * jt][3]);
                float f0 = ex2(SC[0][2 * jt + 1][0]), f1 = ex2(SC[0][2 * jt + 1][1]);
                float f2 = ex2(SC[0][2 * jt + 1][2]), f3 = ex2(SC[0][2 * jt + 1][3]);
                rl[0][0] += (e0 + e1) + (f0 + f1);
                rl[0][1] += (e2 + e3) + (f2 + f3);
                aA0 = packbf16(e0, e1); aA1 = packbf16(e2, e3);
                aA2 = packbf16(f0, f1); aA3 = packbf16(f2, f3);
            }
            {
                float e0 = ex2(SC[1][2 * jt][0]),     e1 = ex2(SC[1][2 * jt][1]);
                float e2 = ex2(SC[1][2 * jt][2]),     e3 = ex2(SC[1][2 * jt][3]);
                float f0 = ex2(SC[1][2 * jt + 1][0]), f1 = ex2(SC[1][2 * jt + 1][1]);
                float f2 = ex2(SC[1][2 * jt + 1][2]), f3 = ex2(SC[1][2 * jt + 1][3]);
                rl[1][0] += (e0 + e1) + (f0 + f1);
                rl[1][1] += (e2 + e3) + (f2 + f3);
                aB0 = packbf16(e0, e1); aB1 = packbf16(e2, e3);
                aB2 = packbf16(f0, f1); aB3 = packbf16(f2, f3);
            }
#pragma unroll
            for (int nt2 = 0; nt2 < 8; nt2++) {
                uint2 vf = Vc[(nt2 * 8 + g) * PV64 + jt * 4 + q];
                mma_bf16(OC[0][nt2], aA0, aA1, aA2, aA3, vf.x, vf.y);
                mma_bf16(OC[1][nt2], aB0, aB1, aB2, aB3, vf.x, vf.y);
            }
        }
    }

    // ---- final row-sum reduction ----
#pragma unroll
    for (int rb = 0; rb < 2; rb++) {
        rl[rb][0] += __shfl_xor_sync(0xffffffffu, rl[rb][0], 1);
        rl[rb][0] += __shfl_xor_sync(0xffffffffu, rl[rb][0], 2);
        rl[rb][1] += __shfl_xor_sync(0xffffffffu, rl[rb][1], 1);
        rl[rb][1] += __shfl_xor_sync(0xffffffffu, rl[rb][1], 2);
    }

    // ---- normalize + write ----
#pragma unroll
    for (int rb = 0; rb < 2; rb++) {
        float inv0 = 1.f / rl[rb][0], inv1 = 1.f / rl[rb][1];
        float* ob = g_attn + (size_t)b * C * NSP + n0 + i0 + rb * 16 + g;
#pragma unroll
        for (int nt2 = 0; nt2 < 8; nt2++) {
            int d0 = nt2 * 8 + 2 * q;
            ob[(size_t)d0 * NSP]           = OC[rb][nt2][0] * inv0;
            ob[(size_t)(d0 + 1) * NSP]     = OC[rb][nt2][1] * inv0;
            ob[(size_t)d0 * NSP + 8]       = OC[rb][nt2][2] * inv1;
            ob[(size_t)(d0 + 1) * NSP + 8] = OC[rb][nt2][3] * inv1;
        }
    }
    #undef ISSUE_CHUNK
}

// ---------------------------------------------------------------------------
// fused tail: depthwise 3x3 + BN2 + ReLU -> smem -> conv1x1 (w3) + BN3 + resid
// CTA = (image row y, batch b); 256 threads.
// phase 1: warp w handles channels w*8..w*8+7, one channel per pass, lanes
//          cover 64 consecutive x via float2 -> fully coalesced loads.
// ---------------------------------------------------------------------------
#define USP 65
__global__ __launch_bounds__(256) void tail_kernel(
    const float* __restrict__ w2,
    const float* __restrict__ g2, const float* __restrict__ b2,
    const float* __restrict__ m2, const float* __restrict__ v2,
    const float* __restrict__ w3,
    const float* __restrict__ g3, const float* __restrict__ b3,
    const float* __restrict__ m3, const float* __restrict__ v3,
    const float* __restrict__ x, float* __restrict__ out)
{
    __shared__ float ws[C * C];
    __shared__ float Us[C * USP];
    __shared__ float s_inv[C], s_shift[C];

    int tid = threadIdx.x;
    int lane = tid & 31;
    int wid = tid >> 5;
    int y = blockIdx.x;
    int b = blockIdx.y;

    for (int i = tid; i < C * C; i += 256) ws[i] = w3[i];
    if (tid < C) {
        float inv = g3[tid] * rsqrtf(v3[tid] + EPSBN);
        s_inv[tid] = inv;
        s_shift[tid] = b3[tid] - m3[tid] * inv;
    }

    // ---- phase 1: depthwise, warp-per-channel passes ----
    {
        int xx = lane * 2;
#pragma unroll
        for (int p = 0; p < 8; p++) {
            int c = wid * 8 + p;
            const float* ip = g_attn + ((size_t)(b * 64 + c) << 12);
            float a0 = 0.f, a1 = 0.f;
#pragma unroll
            for (int dy = -1; dy <= 1; dy++) {
                int yy = y + dy;
                if (yy < 0 || yy >= HW) continue;
                const float* rp = ip + yy * HW + xx;
                float2 mid = *(const float2*)rp;
                float lft = (xx > 0) ? rp[-1] : 0.f;
                float rgt = (xx + 2 < HW) ? rp[2] : 0.f;
                float c0 = w2[c * 9 + (dy + 1) * 3 + 0];
                float c1 = w2[c * 9 + (dy + 1) * 3 + 1];
                float c2 = w2[c * 9 + (dy + 1) * 3 + 2];
                a0 += c0 * lft   + c1 * mid.x + c2 * mid.y;
                a1 += c0 * mid.x + c1 * mid.y + c2 * rgt;
            }
            float inv = g2[c] * rsqrtf(v2[c] + EPSBN);
            float sh = b2[c] - m2[c] * inv;
            Us[c * USP + xx]     = fmaxf(a0 * inv + sh, 0.f);
            Us[c * USP + xx + 1] = fmaxf(a1 * inv + sh, 0.f);
        }
    }
    __syncthreads();

    // ---- phase 2: conv1x1 + BN3 + residual ----
    {
        int xx = tid & 63, h = tid >> 6;
        int n = y * HW + xx;
        float uv[C];
#pragma unroll
        for (int c = 0; c < C; c++) uv[c] = Us[c * USP + xx];

        const float* xp = x + (size_t)b * C * NSP + n;
        float* op = out + (size_t)b * C * NSP + n;
        int o0 = h * 16;
#pragma unroll 4
        for (int o = o0; o < o0 + 16; o++) {
            const float4* wrr = (const float4*)(ws + o * C);
            float a0 = 0.f, a1 = 0.f, a2 = 0.f, a3 = 0.f;
#pragma unroll
            for (int k = 0; k < 16; k++) {
                float4 f = wrr[k];
                a0 += f.x * uv[4 * k + 0];
                a1 += f.y * uv[4 * k + 1];
                a2 += f.z * uv[4 * k + 2];
                a3 += f.w * uv[4 * k + 3];
            }
            float acc = (a0 + a1) + (a2 + a3);
            float r = acc * s_inv[o] + s_shift[o] + xp[(size_t)o * NSP];
            op[(size_t)o * NSP] = r;
        }
    }
}

// ---------------------------------------------------------------------------
extern "C" void kernel_launch(void* const* d_in, const int* in_sizes, int n_in,
                              void* d_out, int out_size)
{
    const float* x    = (const float*)d_in[0];
    const float* w1   = (const float*)d_in[1];
    const float* bn1g = (const float*)d_in[2];
    const float* bn1b = (const float*)d_in[3];
    const float* bn1m = (const float*)d_in[4];
    const float* bn1v = (const float*)d_in[5];
    const float* w2   = (const float*)d_in[6];
    const float* bn2g = (const float*)d_in[7];
    const float* bn2b = (const float*)d_in[8];
    const float* bn2m = (const float*)d_in[9];
    const float* bn2v = (const float*)d_in[10];
    const float* w3   = (const float*)d_in[11];
    const float* bn3g = (const float*)d_in[12];
    const float* bn3b = (const float*)d_in[13];
    const float* bn3m = (const float*)d_in[14];
    const float* bn3v = (const float*)d_in[15];
    float* out = (float*)d_out;

    conv1_kernel<<<dim3(NSP / 64, BB), 256>>>(x, w1, bn1g, bn1b, bn1m, bn1v);
    attn_mma_kernel<<<dim3(NSP / TNQ, BB), 256>>>(x);
    tail_kernel<<<dim3(HW, BB), 256>>>(w2, bn2g, bn2b, bn2m, bn2v,
                                       w3, bn3g, bn3b, bn3m, bn3v, x, out);
}

// round 11
// speedup vs baseline: 1.0329x; 1.0329x over previous
#include <cuda_runtime.h>
#include <cuda_bf16.h>
#include <math.h>

#define C   64
#define HW  64
#define NSP 4096          // N = HW*HW spatial positions
#define BB  8             // batch
#define EPSBN 1e-5f

// attention tiling
#define TNQ 256           // query rows per CTA (8 warps x 32 rows)
#define TMK 64            // key/value chunk
#define PK64 68           // K smem pitch (u64): [16 slots][64 j]
#define PV64 20           // V smem pitch (u64): [64 d][16 slots]

// scale: (1/8) * log2(e)  -> logits in log2 domain, exp == exp2
#define QSCALE 0.18033688f

// scratch (no allocations allowed -> device globals)
__device__ unsigned long long g_K64[BB * 16 * NSP];
__device__ unsigned long long g_V64[BB * 64 * 64 * 16];
__device__ float g_attn[BB * C * NSP];       // attention output

// ---------------------------------------------------------------------------
// helpers
// ---------------------------------------------------------------------------
__device__ __forceinline__ unsigned packbf16(float lo, float hi) {
    unsigned r;
    asm("cvt.rn.bf16x2.f32 %0, %1, %2;" : "=r"(r) : "f"(hi), "f"(lo));
    return r;
}

__device__ __forceinline__ float ex2(float x) {
    float r;
    asm("ex2.approx.ftz.f32 %0, %1;" : "=f"(r) : "f"(x));
    return r;
}

__device__ __forceinline__ void mma_bf16(float c[4],
                                         unsigned a0, unsigned a1, unsigned a2, unsigned a3,
                                         unsigned b0, unsigned b1) {
    asm volatile(
        "mma.sync.aligned.m16n8k16.row.col.f32.bf16.bf16.f32 "
        "{%0,%1,%2,%3},{%4,%5,%6,%7},{%8,%9},{%0,%1,%2,%3};\n"
        : "+f"(c[0]), "+f"(c[1]), "+f"(c[2]), "+f"(c[3])
        : "r"(a0), "r"(a1), "r"(a2), "r"(a3), "r"(b0), "r"(b1));
}

__device__ __forceinline__ void cpa16(unsigned smem_addr, const void* gptr) {
    asm volatile("cp.async.cg.shared.global [%0], [%1], 16;"
                 :: "r"(smem_addr), "l"(gptr));
}

// ---------------------------------------------------------------------------
// conv1x1 (w1) + BN1 + ReLU -> g_V64 (bf16x2, fragment-pair packed)
// also packs K = x into g_K64 (bf16x2, fragment-pair packed)
// ---------------------------------------------------------------------------
__global__ __launch_bounds__(256) void conv1_kernel(
    const float* __restrict__ x, const float* __restrict__ w1,
    const float* __restrict__ g, const float* __restrict__ bb,
    const float* __restrict__ m, const float* __restrict__ v)
{
    __shared__ float ws[C * C];
    __shared__ float s_inv[C], s_shift[C];
    int tid = threadIdx.x;
    for (int i = tid; i < C * C; i += 256) ws[i] = w1[i];
    if (tid < C) {
        float inv = g[tid] * rsqrtf(v[tid] + EPSBN);
        s_inv[tid] = inv;
        s_shift[tid] = bb[tid] - m[tid] * inv;
    }
    __syncthreads();

    int h = tid >> 7;                 // output half (warp-uniform)
    int p = tid & 127;
    int b = blockIdx.y;
    int n = blockIdx.x * 128 + p;
    const float* xp = x + (size_t)b * C * NSP + n;
    float xv[C];
#pragma unroll
    for (int c = 0; c < C; c++) xv[c] = xp[(size_t)c * NSP];

    // ---- K packing (h==0 threads): 16 u64 slots per position ----
    if (h == 0) {
        unsigned long long* kp = g_K64 + (size_t)b * 16 * NSP + n;
#pragma unroll
        for (int s = 0; s < 16; s++) {
            int ks = s >> 2, q = s & 3;
            int dlo = ks * 8 + q, dhi = dlo + 4;
            unsigned lo = packbf16(xv[2 * dlo], xv[2 * dlo + 1]);
            unsigned hi = packbf16(xv[2 * dhi], xv[2 * dhi + 1]);
            kp[(size_t)s * NSP] = (unsigned long long)lo | ((unsigned long long)hi << 32);
        }
    }

    // ---- conv + BN + ReLU into registers ----
    float vout[32];
    int o0 = h * 32;
#pragma unroll 4
    for (int oo = 0; oo < 32; oo++) {
        int o = o0 + oo;
        const float4* wr = (const float4*)(ws + o * C);
        float a0 = 0.f, a1 = 0.f, a2 = 0.f, a3 = 0.f;
#pragma unroll
        for (int k = 0; k < 16; k++) {
            float4 f = wr[k];
            a0 += f.x * xv[4 * k + 0];
            a1 += f.y * xv[4 * k + 1];
            a2 += f.z * xv[4 * k + 2];
            a3 += f.w * xv[4 * k + 3];
        }
        float acc = (a0 + a1) + (a2 + a3);
        vout[oo] = fmaxf(acc * s_inv[o] + s_shift[o], 0.f);
    }

    // ---- V packing: n-pairs via shuffle, write u32 half of u64 slot ----
    {
        bool evenl = !(n & 1);
        int np = n >> 1;
        int ch = n >> 6;
        int jp = np & 31;
        int qq = jp & 7, jt = jp >> 3;
        int t = (qq < 4) ? (jt * 4 + qq) : (jt * 4 + qq - 4);
        int half = (qq < 4) ? 0 : 1;
        unsigned* vp32 = (unsigned*)g_V64;
#pragma unroll
        for (int oo = 0; oo < 32; oo++) {
            float other = __shfl_down_sync(0xffffffffu, vout[oo], 1);
            if (evenl) {
                int d = o0 + oo;
                size_t idx = ((((size_t)b * 64 + d) * 64 + ch) * 16 + t) * 2 + half;
                vp32[idx] = packbf16(vout[oo], other);
            }
        }
    }
}

// ---------------------------------------------------------------------------
// flash attention, bf16 m16n8k16, no-max softmax, Q in regs,
// K/V double-buffered cp.async; fragment pairs as single LDS.64. (R7 verbatim)
// ---------------------------------------------------------------------------
__global__ __launch_bounds__(256) void attn_mma_kernel(const float* __restrict__ x)
{
    __shared__ __align__(16) unsigned long long Ks64[2][16 * PK64];
    __shared__ __align__(16) unsigned long long Vs64[2][64 * PV64];

    const int tid  = threadIdx.x;
    const int lane = tid & 31;
    const int wid  = tid >> 5;
    const int g    = lane >> 2;       // 0..7
    const int q    = lane & 3;        // 0..3
    const int i0   = wid * 32;

    const int b  = blockIdx.y;
    const int n0 = blockIdx.x * TNQ;
    const float* xb = x + (size_t)b * C * NSP;
    const unsigned long long* kb64 = g_K64 + (size_t)b * 16 * NSP;
    const unsigned long long* vb64 = g_V64 + (size_t)b * 64 * 64 * 16;

    unsigned ksa[2], vsa[2];
    ksa[0] = (unsigned)__cvta_generic_to_shared(&Ks64[0][0]);
    ksa[1] = (unsigned)__cvta_generic_to_shared(&Ks64[1][0]);
    vsa[0] = (unsigned)__cvta_generic_to_shared(&Vs64[0][0]);
    vsa[1] = (unsigned)__cvta_generic_to_shared(&Vs64[1][0]);
    const int i2  = tid * 2;
    const int i2b = i2 + 512;

    // ---- Q A-fragments straight into registers (scale folded) ----
    unsigned QA[4][2][4];
#pragma unroll
    for (int ks = 0; ks < 4; ks++) {
#pragma unroll
        for (int rb = 0; rb < 2; rb++) {
            int re = n0 + i0 + rb * 16 + g;
            int d0 = 16 * ks + 2 * q;
            QA[ks][rb][0] = packbf16(xb[(size_t)d0 * NSP + re] * QSCALE,
                                     xb[(size_t)(d0 + 1) * NSP + re] * QSCALE);
            QA[ks][rb][1] = packbf16(xb[(size_t)d0 * NSP + re + 8] * QSCALE,
                                     xb[(size_t)(d0 + 1) * NSP + re + 8] * QSCALE);
            QA[ks][rb][2] = packbf16(xb[(size_t)(d0 + 8) * NSP + re] * QSCALE,
                                     xb[(size_t)(d0 + 9) * NSP + re] * QSCALE);
            QA[ks][rb][3] = packbf16(xb[(size_t)(d0 + 8) * NSP + re + 8] * QSCALE,
                                     xb[(size_t)(d0 + 9) * NSP + re + 8] * QSCALE);
        }
    }

    float SC[2][8][4];
    float OC[2][8][4];
    unsigned PH[2][8][2];
#pragma unroll
    for (int rb = 0; rb < 2; rb++)
#pragma unroll
        for (int t = 0; t < 8; t++)
            OC[rb][t][0] = OC[rb][t][1] = OC[rb][t][2] = OC[rb][t][3] = 0.f;
    float rl[2][2] = {{0.f, 0.f}, {0.f, 0.f}};

    #define ISSUE_CHUNK(m0, buf) do {                                                   \
        int _ch = (m0) >> 6;                                                            \
        cpa16(ksa[buf] + ((i2  >> 6) * PK64 + (i2  & 63)) * 8,                          \
              kb64 + (size_t)(i2  >> 6) * NSP + (m0) + (i2  & 63));                     \
        cpa16(ksa[buf] + ((i2b >> 6) * PK64 + (i2b & 63)) * 8,                          \
              kb64 + (size_t)(i2b >> 6) * NSP + (m0) + (i2b & 63));                     \
        cpa16(vsa[buf] + ((i2  >> 4) * PV64 + (i2  & 15)) * 8,                          \
              vb64 + (size_t)((i2  >> 4) * 64 + _ch) * 16 + (i2  & 15));                \
        cpa16(vsa[buf] + ((i2b >> 4) * PV64 + (i2b & 15)) * 8,                          \
              vb64 + (size_t)((i2b >> 4) * 64 + _ch) * 16 + (i2b & 15));                \
        asm volatile("cp.async.commit_group;");                                         \
    } while (0)

    ISSUE_CHUNK(0, 0);

    for (int mm = 0; mm < NSP / TMK; mm++) {
        int cur = mm & 1;
        if (mm + 1 < NSP / TMK) {
            ISSUE_CHUNK((mm + 1) * TMK, 1 - cur);
            asm volatile("cp.async.wait_group 1;");
        } else {
            asm volatile("cp.async.wait_group 0;");
        }
        __syncthreads();

        const uint2* Kc = (const uint2*)&Ks64[cur][0];
        const uint2* Vc = (const uint2*)&Vs64[cur][0];

        // ---- S = Q K^T ----
#pragma unroll
        for (int rb = 0; rb < 2; rb++)
#pragma unroll
            for (int t = 0; t < 8; t++)
                SC[rb][t][0] = SC[rb][t][1] = SC[rb][t][2] = SC[rb][t][3] = 0.f;
#pragma unroll
        for (int ks = 0; ks < 4; ks++) {
            int srow = (ks * 4 + q) * PK64;
#pragma unroll
            for (int nt = 0; nt < 8; nt++) {
                uint2 kf = Kc[srow + nt * 8 + g];
                mma_bf16(SC[0][nt], QA[ks][0][0], QA[ks][0][1], QA[ks][0][2], QA[ks][0][3], kf.x, kf.y);
                mma_bf16(SC[1][nt], QA[ks][1][0], QA[ks][1][1], QA[ks][1][2], QA[ks][1][3], kf.x, kf.y);
            }
        }

        // ---- P = exp2(S); row sums; pack to A-fragments ----
#pragma unroll
        for (int rb = 0; rb < 2; rb++) {
#pragma unroll
            for (int nt = 0; nt < 8; nt++) {
                float e0 = ex2(SC[rb][nt][0]);
                float e1 = ex2(SC[rb][nt][1]);
                float e2 = ex2(SC[rb][nt][2]);
                float e3 = ex2(SC[rb][nt][3]);
                rl[rb][0] += e0 + e1;
                rl[rb][1] += e2 + e3;
                PH[rb][nt][0] = packbf16(e0, e1);
                PH[rb][nt][1] = packbf16(e2, e3);
            }
        }

        // ---- O += P V ----
#pragma unroll
        for (int jt = 0; jt < 4; jt++) {
            unsigned aA0 = PH[0][2 * jt][0],     aA1 = PH[0][2 * jt][1];
            unsigned aA2 = PH[0][2 * jt + 1][0], aA3 = PH[0][2 * jt + 1][1];
            unsigned aB0 = PH[1][2 * jt][0],     aB1 = PH[1][2 * jt][1];
            unsigned aB2 = PH[1][2 * jt + 1][0], aB3 = PH[1][2 * jt + 1][1];
#pragma unroll
            for (int nt2 = 0; nt2 < 8; nt2++) {
                uint2 vf = Vc[(nt2 * 8 + g) * PV64 + jt * 4 + q];
                mma_bf16(OC[0][nt2], aA0, aA1, aA2, aA3, vf.x, vf.y);
                mma_bf16(OC[1][nt2], aB0, aB1, aB2, aB3, vf.x, vf.y);
            }
        }
        __syncthreads();
    }

    // ---- final row-sum reduction ----
#pragma unroll
    for (int rb = 0; rb < 2; rb++) {
        rl[rb][0] += __shfl_xor_sync(0xffffffffu, rl[rb][0], 1);
        rl[rb][0] += __shfl_xor_sync(0xffffffffu, rl[rb][0], 2);
        rl[rb][1] += __shfl_xor_sync(0xffffffffu, rl[rb][1], 1);
        rl[rb][1] += __shfl_xor_sync(0xffffffffu, rl[rb][1], 2);
    }

    // ---- normalize + write ----
#pragma unroll
    for (int rb = 0; rb < 2; rb++) {
        float inv0 = 1.f / rl[rb][0], inv1 = 1.f / rl[rb][1];
        float* ob = g_attn + (size_t)b * C * NSP + n0 + i0 + rb * 16 + g;
#pragma unroll
        for (int nt2 = 0; nt2 < 8; nt2++) {
            int d0 = nt2 * 8 + 2 * q;
            ob[(size_t)d0 * NSP]           = OC[rb][nt2][0] * inv0;
            ob[(size_t)(d0 + 1) * NSP]     = OC[rb][nt2][1] * inv0;
            ob[(size_t)d0 * NSP + 8]       = OC[rb][nt2][2] * inv1;
            ob[(size_t)(d0 + 1) * NSP + 8] = OC[rb][nt2][3] * inv1;
        }
    }
    #undef ISSUE_CHUNK
}

// ---------------------------------------------------------------------------
// fused tail: depthwise 3x3 + BN2 + ReLU -> smem -> conv1x1 (w3) + BN3 + resid
// CTA = (image row y, batch b); 256 threads.
// phase 1: warp w handles channels w*8..w*8+7, one channel per pass, lanes
//          cover 64 consecutive x via float2 -> fully coalesced loads.
// ---------------------------------------------------------------------------
#define USP 65
__global__ __launch_bounds__(256) void tail_kernel(
    const float* __restrict__ w2,
    const float* __restrict__ g2, const float* __restrict__ b2,
    const float* __restrict__ m2, const float* __restrict__ v2,
    const float* __restrict__ w3,
    const float* __restrict__ g3, const float* __restrict__ b3,
    const float* __restrict__ m3, const float* __restrict__ v3,
    const float* __restrict__ x, float* __restrict__ out)
{
    __shared__ float ws[C * C];
    __shared__ float Us[C * USP];
    __shared__ float s_inv[C], s_shift[C];

    int tid = threadIdx.x;
    int lane = tid & 31;
    int wid = tid >> 5;
    int y = blockIdx.x;
    int b = blockIdx.y;

    for (int i = tid; i < C * C; i += 256) ws[i] = w3[i];
    if (tid < C) {
        float inv = g3[tid] * rsqrtf(v3[tid] + EPSBN);
        s_inv[tid] = inv;
        s_shift[tid] = b3[tid] - m3[tid] * inv;
    }

    // ---- phase 1: depthwise, warp-per-channel passes (coalesced) ----
    {
        int xx = lane * 2;
#pragma unroll
        for (int p = 0; p < 8; p++) {
            int c = wid * 8 + p;
            const float* ip = g_attn + ((size_t)(b * 64 + c) << 12);
            float a0 = 0.f, a1 = 0.f;
#pragma unroll
            for (int dy = -1; dy <= 1; dy++) {
                int yy = y + dy;
                if (yy < 0 || yy >= HW) continue;
                const float* rp = ip + yy * HW + xx;
                float2 mid = *(const float2*)rp;
                float lft = (xx > 0) ? rp[-1] : 0.f;
                float rgt = (xx + 2 < HW) ? rp[2] : 0.f;
                float c0 = w2[c * 9 + (dy + 1) * 3 + 0];
                float c1 = w2[c * 9 + (dy + 1) * 3 + 1];
                float c2 = w2[c * 9 + (dy + 1) * 3 + 2];
                a0 += c0 * lft   + c1 * mid.x + c2 * mid.y;
                a1 += c0 * mid.x + c1 * mid.y + c2 * rgt;
            }
            float inv = g2[c] * rsqrtf(v2[c] + EPSBN);
            float sh = b2[c] - m2[c] * inv;
            Us[c * USP + xx]     = fmaxf(a0 * inv + sh, 0.f);
            Us[c * USP + xx + 1] = fmaxf(a1 * inv + sh, 0.f);
        }
    }
    __syncthreads();

    // ---- phase 2: conv1x1 + BN3 + residual ----
    {
        int xx = tid & 63, h = tid >> 6;
        int n = y * HW + xx;
        float uv[C];
#pragma unroll
        for (int c = 0; c < C; c++) uv[c] = Us[c * USP + xx];

        const float* xp = x + (size_t)b * C * NSP + n;
        float* op = out + (size_t)b * C * NSP + n;
        int o0 = h * 16;
#pragma unroll 4
        for (int o = o0; o < o0 + 16; o++) {
            const float4* wrr = (const float4*)(ws + o * C);
            float a0 = 0.f, a1 = 0.f, a2 = 0.f, a3 = 0.f;
#pragma unroll
            for (int k = 0; k < 16; k++) {
                float4 f = wrr[k];
                a0 += f.x * uv[4 * k + 0];
                a1 += f.y * uv[4 * k + 1];
                a2 += f.z * uv[4 * k + 2];
                a3 += f.w * uv[4 * k + 3];
            }
            float acc = (a0 + a1) + (a2 + a3);
            float r = acc * s_inv[o] + s_shift[o] + xp[(size_t)o * NSP];
            op[(size_t)o * NSP] = r;
        }
    }
}

// ---------------------------------------------------------------------------
extern "C" void kernel_launch(void* const* d_in, const int* in_sizes, int n_in,
                              void* d_out, int out_size)
{
    const float* x    = (const float*)d_in[0];
    const float* w1   = (const float*)d_in[1];
    const float* bn1g = (const float*)d_in[2];
    const float* bn1b = (const float*)d_in[3];
    const float* bn1m = (const float*)d_in[4];
    const float* bn1v = (const float*)d_in[5];
    const float* w2   = (const float*)d_in[6];
    const float* bn2g = (const float*)d_in[7];
    const float* bn2b = (const float*)d_in[8];
    const float* bn2m = (const float*)d_in[9];
    const float* bn2v = (const float*)d_in[10];
    const float* w3   = (const float*)d_in[11];
    const float* bn3g = (const float*)d_in[12];
    const float* bn3b = (const float*)d_in[13];
    const float* bn3m = (const float*)d_in[14];
    const float* bn3v = (const float*)d_in[15];
    float* out = (float*)d_out;

    conv1_kernel<<<dim3(NSP / 128, BB), 256>>>(x, w1, bn1g, bn1b, bn1m, bn1v);
    attn_mma_kernel<<<dim3(NSP / TNQ, BB), 256>>>(x);
    tail_kernel<<<dim3(HW, BB), 256>>>(w2, bn2g, bn2b, bn2m, bn2v,
                                       w3, bn3g, bn3b, bn3m, bn3v, x, out);
}

// round 12
// speedup vs baseline: 1.1937x; 1.1557x over previous
#include <cuda_runtime.h>
#include <cuda_bf16.h>
#include <math.h>

#define C   64
#define HW  64
#define NSP 4096          // N = HW*HW spatial positions
#define BB  8             // batch
#define EPSBN 1e-5f

// attention tiling
#define TNQ 256           // query rows per CTA (8 warps x 32 rows)
#define TMK 64            // key/value chunk
#define PK64 68           // K smem pitch (u64): [16 slots][64 j]
#define PV64 20           // V smem pitch (u64): [64 d][16 slots]

// conv1 mma smem pitches (u64, mod 16 == 4 for conflict-free LDS.64)
#define PB1 132           // x tile  [16 slots][128 n]
#define PW1 20            // weights [64 rows][16 slots]

// scale: (1/8) * log2(e)  -> logits in log2 domain, exp == exp2
#define QSCALE 0.18033688f

// scratch (no allocations allowed -> device globals)
__device__ unsigned long long g_K64[BB * 16 * NSP];
__device__ unsigned long long g_V64[BB * 64 * 64 * 16];
__device__ float g_attn[BB * C * NSP];       // attention output

// ---------------------------------------------------------------------------
// helpers
// ---------------------------------------------------------------------------
__device__ __forceinline__ unsigned packbf16(float lo, float hi) {
    unsigned r;
    asm("cvt.rn.bf16x2.f32 %0, %1, %2;" : "=r"(r) : "f"(hi), "f"(lo));
    return r;
}

__device__ __forceinline__ unsigned f2tf32(float f) {
    unsigned u;
    asm("cvt.rna.tf32.f32 %0, %1;" : "=r"(u) : "f"(f));
    return u;
}

__device__ __forceinline__ float ex2(float x) {
    float r;
    asm("ex2.approx.ftz.f32 %0, %1;" : "=f"(r) : "f"(x));
    return r;
}

__device__ __forceinline__ void mma_bf16(float c[4],
                                         unsigned a0, unsigned a1, unsigned a2, unsigned a3,
                                         unsigned b0, unsigned b1) {
    asm volatile(
        "mma.sync.aligned.m16n8k16.row.col.f32.bf16.bf16.f32 "
        "{%0,%1,%2,%3},{%4,%5,%6,%7},{%8,%9},{%0,%1,%2,%3};\n"
        : "+f"(c[0]), "+f"(c[1]), "+f"(c[2]), "+f"(c[3])
        : "r"(a0), "r"(a1), "r"(a2), "r"(a3), "r"(b0), "r"(b1));
}

__device__ __forceinline__ void mma_tf32(float c[4],
                                         unsigned a0, unsigned a1, unsigned a2, unsigned a3,
                                         unsigned b0, unsigned b1) {
    asm volatile(
        "mma.sync.aligned.m16n8k8.row.col.f32.tf32.tf32.f32 "
        "{%0,%1,%2,%3},{%4,%5,%6,%7},{%8,%9},{%0,%1,%2,%3};\n"
        : "+f"(c[0]), "+f"(c[1]), "+f"(c[2]), "+f"(c[3])
        : "r"(a0), "r"(a1), "r"(a2), "r"(a3), "r"(b0), "r"(b1));
}

__device__ __forceinline__ void cpa16(unsigned smem_addr, const void* gptr) {
    asm volatile("cp.async.cg.shared.global [%0], [%1], 16;"
                 :: "r"(smem_addr), "l"(gptr));
}

// ---------------------------------------------------------------------------
// conv1 via bf16 mma: packs x -> g_K64 (and SMEM), computes V = BN1(W1 x)+,
// packs V -> g_V64. CTA = (batch, 128 positions); 8 warps x 16 positions.
// ---------------------------------------------------------------------------
__global__ __launch_bounds__(256) void conv1_mma_kernel(
    const float* __restrict__ x, const float* __restrict__ w1,
    const float* __restrict__ g, const float* __restrict__ bb,
    const float* __restrict__ m, const float* __restrict__ v)
{
    __shared__ __align__(16) unsigned long long Bs[16 * PB1];   // x tile packed
    __shared__ __align__(16) unsigned long long Ws[64 * PW1];   // w1 packed
    __shared__ float s_inv[C], s_shift[C];

    const int tid  = threadIdx.x;
    const int lane = tid & 31;
    const int wid  = tid >> 5;
    const int gq_g = lane >> 2;       // 0..7
    const int gq_q = lane & 3;        // 0..3

    const int b  = blockIdx.y;
    const int n0 = blockIdx.x * 128;
    const float* xb = x + (size_t)b * C * NSP;

    // ---- step 1: pack x tile -> SMEM Bs + GMEM g_K64 ----
    // u64 slot s (=ks*4+q): lo = bf16x2(ch 16ks+2q, +1), hi = (ch +8, +9)
    {
        unsigned long long* kp = g_K64 + (size_t)b * 16 * NSP;
#pragma unroll
        for (int i = 0; i < 8; i++) {
            int idx = tid + i * 256;          // 0..2047
            int s = idx >> 7, n = idx & 127;
            int ks = s >> 2, q = s & 3;
            int c0 = 16 * ks + 2 * q;
            float xl0 = xb[(size_t)c0 * NSP + n0 + n];
            float xl1 = xb[(size_t)(c0 + 1) * NSP + n0 + n];
            float xh0 = xb[(size_t)(c0 + 8) * NSP + n0 + n];
            float xh1 = xb[(size_t)(c0 + 9) * NSP + n0 + n];
            unsigned lo = packbf16(xl0, xl1);
            unsigned hi = packbf16(xh0, xh1);
            unsigned long long u = (unsigned long long)lo | ((unsigned long long)hi << 32);
            Bs[s * PB1 + n] = u;
            kp[(size_t)s * NSP + n0 + n] = u;
        }
    }

    // ---- step 2: pack w1 -> SMEM Ws (A-fragment u64 slots) ----
    {
#pragma unroll
        for (int i = 0; i < 4; i++) {
            int idx = tid + i * 256;          // 0..1023
            int r = idx >> 4, s = idx & 15;
            int ks = s >> 2, q = s & 3;
            const float* wr = w1 + r * 64 + 16 * ks + 2 * q;
            float2 wl = *(const float2*)wr;
            float2 wh = *(const float2*)(wr + 8);
            unsigned lo = packbf16(wl.x, wl.y);
            unsigned hi = packbf16(wh.x, wh.y);
            Ws[r * PW1 + s] = (unsigned long long)lo | ((unsigned long long)hi << 32);
        }
    }
    if (tid < C) {
        float inv = g[tid] * rsqrtf(v[tid] + EPSBN);
        s_inv[tid] = inv;
        s_shift[tid] = bb[tid] - m[tid] * inv;
    }
    __syncthreads();

    // ---- step 3: GEMM  O[64 x 16] per warp (warp covers n = w*16..w*16+15)
    float OC[4][2][4];                // [mt][nt][frag]
#pragma unroll
    for (int mt = 0; mt < 4; mt++)
#pragma unroll
        for (int nt = 0; nt < 2; nt++)
            OC[mt][nt][0] = OC[mt][nt][1] = OC[mt][nt][2] = OC[mt][nt][3] = 0.f;

    const uint2* Bc = (const uint2*)Bs;
    const uint2* Wc = (const uint2*)Ws;
#pragma unroll
    for (int ks = 0; ks < 4; ks++) {
        int srow = (ks * 4 + gq_q);
        uint2 bf0 = Bc[srow * PB1 + wid * 16 + 0 * 8 + gq_g];
        uint2 bf1 = Bc[srow * PB1 + wid * 16 + 1 * 8 + gq_g];
#pragma unroll
        for (int mt = 0; mt < 4; mt++) {
            uint2 afl = Wc[(mt * 16 + gq_g) * PW1 + srow];      // a0, a2
            uint2 afh = Wc[(mt * 16 + gq_g + 8) * PW1 + srow];  // a1, a3
            mma_bf16(OC[mt][0], afl.x, afh.x, afl.y, afh.y, bf0.x, bf0.y);
            mma_bf16(OC[mt][1], afl.x, afh.x, afl.y, afh.y, bf1.x, bf1.y);
        }
    }

    // ---- step 4: BN1 + ReLU + pack n-pairs -> g_V64 ----
    // cols per (nt): n = n0 + wid*16 + nt*8 + 2q (and +1) -> jp pair index:
    // t = (wid&3)*4 + q, half = nt, ch = 2*blockIdx.x + (wid>>2)
    {
        unsigned* vp32 = (unsigned*)g_V64;
        int t = (wid & 3) * 4 + gq_q;
        int ch = 2 * blockIdx.x + (wid >> 2);
#pragma unroll
        for (int mt = 0; mt < 4; mt++) {
            int d0 = mt * 16 + gq_g;
            float i0v = s_inv[d0], sh0 = s_shift[d0];
            float i1v = s_inv[d0 + 8], sh1 = s_shift[d0 + 8];
#pragma unroll
            for (int nt = 0; nt < 2; nt++) {
                float v00 = fmaxf(OC[mt][nt][0] * i0v + sh0, 0.f);
                float v01 = fmaxf(OC[mt][nt][1] * i0v + sh0, 0.f);
                float v10 = fmaxf(OC[mt][nt][2] * i1v + sh1, 0.f);
                float v11 = fmaxf(OC[mt][nt][3] * i1v + sh1, 0.f);
                size_t base0 = ((((size_t)b * 64 + d0) * 64 + ch) * 16 + t) * 2 + nt;
                size_t base1 = ((((size_t)b * 64 + d0 + 8) * 64 + ch) * 16 + t) * 2 + nt;
                vp32[base0] = packbf16(v00, v01);
                vp32[base1] = packbf16(v10, v11);
            }
        }
    }
}

// ---------------------------------------------------------------------------
// flash attention, bf16 m16n8k16, no-max softmax, Q in regs,
// K/V double-buffered cp.async; fragment pairs as single LDS.64. (R7 verbatim)
// ---------------------------------------------------------------------------
__global__ __launch_bounds__(256) void attn_mma_kernel(const float* __restrict__ x)
{
    __shared__ __align__(16) unsigned long long Ks64[2][16 * PK64];
    __shared__ __align__(16) unsigned long long Vs64[2][64 * PV64];

    const int tid  = threadIdx.x;
    const int lane = tid & 31;
    const int wid  = tid >> 5;
    const int g    = lane >> 2;       // 0..7
    const int q    = lane & 3;        // 0..3
    const int i0   = wid * 32;

    const int b  = blockIdx.y;
    const int n0 = blockIdx.x * TNQ;
    const float* xb = x + (size_t)b * C * NSP;
    const unsigned long long* kb64 = g_K64 + (size_t)b * 16 * NSP;
    const unsigned long long* vb64 = g_V64 + (size_t)b * 64 * 64 * 16;

    unsigned ksa[2], vsa[2];
    ksa[0] = (unsigned)__cvta_generic_to_shared(&Ks64[0][0]);
    ksa[1] = (unsigned)__cvta_generic_to_shared(&Ks64[1][0]);
    vsa[0] = (unsigned)__cvta_generic_to_shared(&Vs64[0][0]);
    vsa[1] = (unsigned)__cvta_generic_to_shared(&Vs64[1][0]);
    const int i2  = tid * 2;
    const int i2b = i2 + 512;

    // ---- Q A-fragments straight into registers (scale folded) ----
    unsigned QA[4][2][4];
#pragma unroll
    for (int ks = 0; ks < 4; ks++) {
#pragma unroll
        for (int rb = 0; rb < 2; rb++) {
            int re = n0 + i0 + rb * 16 + g;
            int d0 = 16 * ks + 2 * q;
            QA[ks][rb][0] = packbf16(xb[(size_t)d0 * NSP + re] * QSCALE,
                                     xb[(size_t)(d0 + 1) * NSP + re] * QSCALE);
            QA[ks][rb][1] = packbf16(xb[(size_t)d0 * NSP + re + 8] * QSCALE,
                                     xb[(size_t)(d0 + 1) * NSP + re + 8] * QSCALE);
            QA[ks][rb][2] = packbf16(xb[(size_t)(d0 + 8) * NSP + re] * QSCALE,
                                     xb[(size_t)(d0 + 9) * NSP + re] * QSCALE);
            QA[ks][rb][3] = packbf16(xb[(size_t)(d0 + 8) * NSP + re + 8] * QSCALE,
                                     xb[(size_t)(d0 + 9) * NSP + re + 8] * QSCALE);
        }
    }

    float SC[2][8][4];
    float OC[2][8][4];
    unsigned PH[2][8][2];
#pragma unroll
    for (int rb = 0; rb < 2; rb++)
#pragma unroll
        for (int t = 0; t < 8; t++)
            OC[rb][t][0] = OC[rb][t][1] = OC[rb][t][2] = OC[rb][t][3] = 0.f;
    float rl[2][2] = {{0.f, 0.f}, {0.f, 0.f}};

    #define ISSUE_CHUNK(m0, buf) do {                                                   \
        int _ch = (m0) >> 6;                                                            \
        cpa16(ksa[buf] + ((i2  >> 6) * PK64 + (i2  & 63)) * 8,                          \
              kb64 + (size_t)(i2  >> 6) * NSP + (m0) + (i2  & 63));                     \
        cpa16(ksa[buf] + ((i2b >> 6) * PK64 + (i2b & 63)) * 8,                          \
              kb64 + (size_t)(i2b >> 6) * NSP + (m0) + (i2b & 63));                     \
        cpa16(vsa[buf] + ((i2  >> 4) * PV64 + (i2  & 15)) * 8,                          \
              vb64 + (size_t)((i2  >> 4) * 64 + _ch) * 16 + (i2  & 15));                \
        cpa16(vsa[buf] + ((i2b >> 4) * PV64 + (i2b & 15)) * 8,                          \
              vb64 + (size_t)((i2b >> 4) * 64 + _ch) * 16 + (i2b & 15));                \
        asm volatile("cp.async.commit_group;");                                         \
    } while (0)

    ISSUE_CHUNK(0, 0);

    for (int mm = 0; mm < NSP / TMK; mm++) {
        int cur = mm & 1;
        if (mm + 1 < NSP / TMK) {
            ISSUE_CHUNK((mm + 1) * TMK, 1 - cur);
            asm volatile("cp.async.wait_group 1;");
        } else {
            asm volatile("cp.async.wait_group 0;");
        }
        __syncthreads();

        const uint2* Kc = (const uint2*)&Ks64[cur][0];
        const uint2* Vc = (const uint2*)&Vs64[cur][0];

        // ---- S = Q K^T ----
#pragma unroll
        for (int rb = 0; rb < 2; rb++)
#pragma unroll
            for (int t = 0; t < 8; t++)
                SC[rb][t][0] = SC[rb][t][1] = SC[rb][t][2] = SC[rb][t][3] = 0.f;
#pragma unroll
        for (int ks = 0; ks < 4; ks++) {
            int srow = (ks * 4 + q) * PK64;
#pragma unroll
            for (int nt = 0; nt < 8; nt++) {
                uint2 kf = Kc[srow + nt * 8 + g];
                mma_bf16(SC[0][nt], QA[ks][0][0], QA[ks][0][1], QA[ks][0][2], QA[ks][0][3], kf.x, kf.y);
                mma_bf16(SC[1][nt], QA[ks][1][0], QA[ks][1][1], QA[ks][1][2], QA[ks][1][3], kf.x, kf.y);
            }
        }

        // ---- P = exp2(S); row sums; pack to A-fragments ----
#pragma unroll
        for (int rb = 0; rb < 2; rb++) {
#pragma unroll
            for (int nt = 0; nt < 8; nt++) {
                float e0 = ex2(SC[rb][nt][0]);
                float e1 = ex2(SC[rb][nt][1]);
                float e2 = ex2(SC[rb][nt][2]);
                float e3 = ex2(SC[rb][nt][3]);
                rl[rb][0] += e0 + e1;
                rl[rb][1] += e2 + e3;
                PH[rb][nt][0] = packbf16(e0, e1);
                PH[rb][nt][1] = packbf16(e2, e3);
            }
        }

        // ---- O += P V ----
#pragma unroll
        for (int jt = 0; jt < 4; jt++) {
            unsigned aA0 = PH[0][2 * jt][0],     aA1 = PH[0][2 * jt][1];
            unsigned aA2 = PH[0][2 * jt + 1][0], aA3 = PH[0][2 * jt + 1][1];
            unsigned aB0 = PH[1][2 * jt][0],     aB1 = PH[1][2 * jt][1];
            unsigned aB2 = PH[1][2 * jt + 1][0], aB3 = PH[1][2 * jt + 1][1];
#pragma unroll
            for (int nt2 = 0; nt2 < 8; nt2++) {
                uint2 vf = Vc[(nt2 * 8 + g) * PV64 + jt * 4 + q];
                mma_bf16(OC[0][nt2], aA0, aA1, aA2, aA3, vf.x, vf.y);
                mma_bf16(OC[1][nt2], aB0, aB1, aB2, aB3, vf.x, vf.y);
            }
        }
        __syncthreads();
    }

    // ---- final row-sum reduction ----
#pragma unroll
    for (int rb = 0; rb < 2; rb++) {
        rl[rb][0] += __shfl_xor_sync(0xffffffffu, rl[rb][0], 1);
        rl[rb][0] += __shfl_xor_sync(0xffffffffu, rl[rb][0], 2);
        rl[rb][1] += __shfl_xor_sync(0xffffffffu, rl[rb][1], 1);
        rl[rb][1] += __shfl_xor_sync(0xffffffffu, rl[rb][1], 2);
    }

    // ---- normalize + write ----
#pragma unroll
    for (int rb = 0; rb < 2; rb++) {
        float inv0 = 1.f / rl[rb][0], inv1 = 1.f / rl[rb][1];
        float* ob = g_attn + (size_t)b * C * NSP + n0 + i0 + rb * 16 + g;
#pragma unroll
        for (int nt2 = 0; nt2 < 8; nt2++) {
            int d0 = nt2 * 8 + 2 * q;
            ob[(size_t)d0 * NSP]           = OC[rb][nt2][0] * inv0;
            ob[(size_t)(d0 + 1) * NSP]     = OC[rb][nt2][1] * inv0;
            ob[(size_t)d0 * NSP + 8]       = OC[rb][nt2][2] * inv1;
            ob[(size_t)(d0 + 1) * NSP + 8] = OC[rb][nt2][3] * inv1;
        }
    }
    #undef ISSUE_CHUNK
}

// ---------------------------------------------------------------------------
// fused tail: dw 3x3 + BN2 + ReLU -> smem; conv1x1 (w3) via tf32 mma + BN3 +
// residual. CTA = (image row y, batch b); 256 threads.
// ---------------------------------------------------------------------------
#define USP 72
#define WSP 68
__global__ __launch_bounds__(256) void tail_kernel(
    const float* __restrict__ w2,
    const float* __restrict__ g2, const float* __restrict__ b2,
    const float* __restrict__ m2, const float* __restrict__ v2,
    const float* __restrict__ w3,
    const float* __restrict__ g3, const float* __restrict__ b3,
    const float* __restrict__ m3, const float* __restrict__ v3,
    const float* __restrict__ x, float* __restrict__ out)
{
    __shared__ float ws[C * WSP];
    __shared__ float Us[C * USP];
    __shared__ float s_inv[C], s_shift[C];

    int tid = threadIdx.x;
    int lane = tid & 31;
    int wid = tid >> 5;
    int y = blockIdx.x;
    int b = blockIdx.y;

    for (int i = tid; i < C * C; i += 256) {
        int r = i >> 6, c = i & 63;
        ws[r * WSP + c] = w3[i];
    }
    if (tid < C) {
        float inv = g3[tid] * rsqrtf(v3[tid] + EPSBN);
        s_inv[tid] = inv;
        s_shift[tid] = b3[tid] - m3[tid] * inv;
    }

    // ---- phase 1: depthwise, warp-per-channel passes (coalesced) ----
    {
        int xx = lane * 2;
#pragma unroll
        for (int p = 0; p < 8; p++) {
            int c = wid * 8 + p;
            const float* ip = g_attn + ((size_t)(b * 64 + c) << 12);
            float a0 = 0.f, a1 = 0.f;
#pragma unroll
            for (int dy = -1; dy <= 1; dy++) {
                int yy = y + dy;
                if (yy < 0 || yy >= HW) continue;
                const float* rp = ip + yy * HW + xx;
                float2 mid = *(const float2*)rp;
                float lft = (xx > 0) ? rp[-1] : 0.f;
                float rgt = (xx + 2 < HW) ? rp[2] : 0.f;
                float c0 = w2[c * 9 + (dy + 1) * 3 + 0];
                float c1 = w2[c * 9 + (dy + 1) * 3 + 1];
                float c2 = w2[c * 9 + (dy + 1) * 3 + 2];
                a0 += c0 * lft   + c1 * mid.x + c2 * mid.y;
                a1 += c0 * mid.x + c1 * mid.y + c2 * rgt;
            }
            float inv = g2[c] * rsqrtf(v2[c] + EPSBN);
            float sh = b2[c] - m2[c] * inv;
            Us[c * USP + xx]     = fmaxf(a0 * inv + sh, 0.f);
            Us[c * USP + xx + 1] = fmaxf(a1 * inv + sh, 0.f);
        }
    }
    __syncthreads();

    // ---- phase 2: conv1x1 via tf32 mma + BN3 + residual ----
    {
        const int g = lane >> 2, q = lane & 3;
        float OC3[4][4];
#pragma unroll
        for (int mt = 0; mt < 4; mt++)
            OC3[mt][0] = OC3[mt][1] = OC3[mt][2] = OC3[mt][3] = 0.f;

#pragma unroll
        for (int ks = 0; ks < 8; ks++) {
            unsigned b0 = f2tf32(Us[(ks * 8 + q) * USP + wid * 8 + g]);
            unsigned b1 = f2tf32(Us[(ks * 8 + q + 4) * USP + wid * 8 + g]);
#pragma unroll
            for (int mt = 0; mt < 4; mt++) {
                unsigned a0 = f2tf32(ws[(mt * 16 + g) * WSP + ks * 8 + q]);
                unsigned a1 = f2tf32(ws[(mt * 16 + g + 8) * WSP + ks * 8 + q]);
                unsigned a2 = f2tf32(ws[(mt * 16 + g) * WSP + ks * 8 + q + 4]);
                unsigned a3 = f2tf32(ws[(mt * 16 + g + 8) * WSP + ks * 8 + q + 4]);
                mma_tf32(OC3[mt], a0, a1, a2, a3, b0, b1);
            }
        }

        // epilogue: rows o = mt*16+g (+8), cols n = y*64 + wid*8 + 2q (+1)
        int n = y * HW + wid * 8 + 2 * q;
        const float* xp = x + (size_t)b * C * NSP + n;
        float* op = out + (size_t)b * C * NSP + n;
#pragma unroll
        for (int mt = 0; mt < 4; mt++) {
            int o0 = mt * 16 + g;
            float i0v = s_inv[o0], sh0 = s_shift[o0];
            float i1v = s_inv[o0 + 8], sh1 = s_shift[o0 + 8];
            op[(size_t)o0 * NSP]           = OC3[mt][0] * i0v + sh0 + xp[(size_t)o0 * NSP];
            op[(size_t)o0 * NSP + 1]       = OC3[mt][1] * i0v + sh0 + xp[(size_t)o0 * NSP + 1];
            op[(size_t)(o0 + 8) * NSP]     = OC3[mt][2] * i1v + sh1 + xp[(size_t)(o0 + 8) * NSP];
            op[(size_t)(o0 + 8) * NSP + 1] = OC3[mt][3] * i1v + sh1 + xp[(size_t)(o0 + 8) * NSP + 1];
        }
    }
}

// ---------------------------------------------------------------------------
extern "C" void kernel_launch(void* const* d_in, const int* in_sizes, int n_in,
                              void* d_out, int out_size)
{
    const float* x    = (const float*)d_in[0];
    const float* w1   = (const float*)d_in[1];
    const float* bn1g = (const float*)d_in[2];
    const float* bn1b = (const float*)d_in[3];
    const float* bn1m = (const float*)d_in[4];
    const float* bn1v = (const float*)d_in[5];
    const float* w2   = (const float*)d_in[6];
    const float* bn2g = (const float*)d_in[7];
    const float* bn2b = (const float*)d_in[8];
    const float* bn2m = (const float*)d_in[9];
    const float* bn2v = (const float*)d_in[10];
    const float* w3   = (const float*)d_in[11];
    const float* bn3g = (const float*)d_in[12];
    const float* bn3b = (const float*)d_in[13];
    const float* bn3m = (const float*)d_in[14];
    const float* bn3v = (const float*)d_in[15];
    float* out = (float*)d_out;

    conv1_mma_kernel<<<dim3(NSP / 128, BB), 256>>>(x, w1, bn1g, bn1b, bn1m, bn1v);
    attn_mma_kernel<<<dim3(NSP / TNQ, BB), 256>>>(x);
    tail_kernel<<<dim3(HW, BB), 256>>>(w2, bn2g, bn2b, bn2m, bn2v,
                                       w3, bn3g, bn3b, bn3m, bn3v, x, out);
}

// round 13
// speedup vs baseline: 1.2159x; 1.0186x over previous
#include <cuda_runtime.h>
#include <cuda_bf16.h>
#include <math.h>

#define C   64
#define HW  64
#define NSP 4096          // N = HW*HW spatial positions
#define BB  8             // batch
#define EPSBN 1e-5f

// attention tiling
#define TNQ 256           // query rows per CTA (8 warps x 32 rows)
#define TMK 64            // key/value chunk
#define PK64 68           // K smem pitch (u64): [16 slots][64 j]
#define PV64 20           // V smem pitch (u64): [64 d][16 slots]

// conv1 mma smem pitches (u64, mod 16 == 4 for conflict-free LDS.64)
#define PB1 132           // x tile  [16 slots][128 n]
#define PW1 20            // weights [64 rows][16 slots]

// scale: (1/8) * log2(e)  -> logits in log2 domain, exp == exp2
#define QSCALE 0.18033688f

// scratch (no allocations allowed -> device globals)
__device__ unsigned long long g_K64[BB * 16 * NSP];
__device__ unsigned long long g_V64[BB * 64 * 64 * 16];
__device__ float g_attn[BB * C * NSP];       // attention output

// ---------------------------------------------------------------------------
// helpers
// ---------------------------------------------------------------------------
__device__ __forceinline__ unsigned packbf16(float lo, float hi) {
    unsigned r;
    asm("cvt.rn.bf16x2.f32 %0, %1, %2;" : "=r"(r) : "f"(hi), "f"(lo));
    return r;
}

__device__ __forceinline__ unsigned f2tf32(float f) {
    unsigned u;
    asm("cvt.rna.tf32.f32 %0, %1;" : "=r"(u) : "f"(f));
    return u;
}

__device__ __forceinline__ float ex2(float x) {
    float r;
    asm("ex2.approx.ftz.f32 %0, %1;" : "=f"(r) : "f"(x));
    return r;
}

__device__ __forceinline__ void mma_bf16(float c[4],
                                         unsigned a0, unsigned a1, unsigned a2, unsigned a3,
                                         unsigned b0, unsigned b1) {
    asm volatile(
        "mma.sync.aligned.m16n8k16.row.col.f32.bf16.bf16.f32 "
        "{%0,%1,%2,%3},{%4,%5,%6,%7},{%8,%9},{%0,%1,%2,%3};\n"
        : "+f"(c[0]), "+f"(c[1]), "+f"(c[2]), "+f"(c[3])
        : "r"(a0), "r"(a1), "r"(a2), "r"(a3), "r"(b0), "r"(b1));
}

__device__ __forceinline__ void mma_tf32(float c[4],
                                         unsigned a0, unsigned a1, unsigned a2, unsigned a3,
                                         unsigned b0, unsigned b1) {
    asm volatile(
        "mma.sync.aligned.m16n8k8.row.col.f32.tf32.tf32.f32 "
        "{%0,%1,%2,%3},{%4,%5,%6,%7},{%8,%9},{%0,%1,%2,%3};\n"
        : "+f"(c[0]), "+f"(c[1]), "+f"(c[2]), "+f"(c[3])
        : "r"(a0), "r"(a1), "r"(a2), "r"(a3), "r"(b0), "r"(b1));
}

__device__ __forceinline__ void cpa16(unsigned smem_addr, const void* gptr) {
    asm volatile("cp.async.cg.shared.global [%0], [%1], 16;"
                 :: "r"(smem_addr), "l"(gptr));
}

// ---------------------------------------------------------------------------
// conv1 via bf16 mma: packs x -> g_K64 (and SMEM), computes V = BN1(W1 x)+,
// packs V -> g_V64. CTA = (batch, 128 positions); 8 warps x 16 positions.
// ---------------------------------------------------------------------------
__global__ __launch_bounds__(256) void conv1_mma_kernel(
    const float* __restrict__ x, const float* __restrict__ w1,
    const float* __restrict__ g, const float* __restrict__ bb,
    const float* __restrict__ m, const float* __restrict__ v)
{
    __shared__ __align__(16) unsigned long long Bs[16 * PB1];   // x tile packed
    __shared__ __align__(16) unsigned long long Ws[64 * PW1];   // w1 packed
    __shared__ float s_inv[C], s_shift[C];

    const int tid  = threadIdx.x;
    const int lane = tid & 31;
    const int wid  = tid >> 5;
    const int gq_g = lane >> 2;       // 0..7
    const int gq_q = lane & 3;        // 0..3

    const int b  = blockIdx.y;
    const int n0 = blockIdx.x * 128;
    const float* xb = x + (size_t)b * C * NSP;

    // ---- step 1: pack x tile -> SMEM Bs + GMEM g_K64 ----
    {
        unsigned long long* kp = g_K64 + (size_t)b * 16 * NSP;
#pragma unroll
        for (int i = 0; i < 8; i++) {
            int idx = tid + i * 256;          // 0..2047
            int s = idx >> 7, n = idx & 127;
            int ks = s >> 2, q = s & 3;
            int c0 = 16 * ks + 2 * q;
            float xl0 = xb[(size_t)c0 * NSP + n0 + n];
            float xl1 = xb[(size_t)(c0 + 1) * NSP + n0 + n];
            float xh0 = xb[(size_t)(c0 + 8) * NSP + n0 + n];
            float xh1 = xb[(size_t)(c0 + 9) * NSP + n0 + n];
            unsigned lo = packbf16(xl0, xl1);
            unsigned hi = packbf16(xh0, xh1);
            unsigned long long u = (unsigned long long)lo | ((unsigned long long)hi << 32);
            Bs[s * PB1 + n] = u;
            kp[(size_t)s * NSP + n0 + n] = u;
        }
    }

    // ---- step 2: pack w1 -> SMEM Ws (A-fragment u64 slots) ----
    {
#pragma unroll
        for (int i = 0; i < 4; i++) {
            int idx = tid + i * 256;          // 0..1023
            int r = idx >> 4, s = idx & 15;
            int ks = s >> 2, q = s & 3;
            const float* wr = w1 + r * 64 + 16 * ks + 2 * q;
            float2 wl = *(const float2*)wr;
            float2 wh = *(const float2*)(wr + 8);
            unsigned lo = packbf16(wl.x, wl.y);
            unsigned hi = packbf16(wh.x, wh.y);
            Ws[r * PW1 + s] = (unsigned long long)lo | ((unsigned long long)hi << 32);
        }
    }
    if (tid < C) {
        float inv = g[tid] * rsqrtf(v[tid] + EPSBN);
        s_inv[tid] = inv;
        s_shift[tid] = bb[tid] - m[tid] * inv;
    }
    __syncthreads();

    // ---- step 3: GEMM  O[64 x 16] per warp ----
    float OC[4][2][4];
#pragma unroll
    for (int mt = 0; mt < 4; mt++)
#pragma unroll
        for (int nt = 0; nt < 2; nt++)
            OC[mt][nt][0] = OC[mt][nt][1] = OC[mt][nt][2] = OC[mt][nt][3] = 0.f;

    const uint2* Bc = (const uint2*)Bs;
    const uint2* Wc = (const uint2*)Ws;
#pragma unroll
    for (int ks = 0; ks < 4; ks++) {
        int srow = (ks * 4 + gq_q);
        uint2 bf0 = Bc[srow * PB1 + wid * 16 + 0 * 8 + gq_g];
        uint2 bf1 = Bc[srow * PB1 + wid * 16 + 1 * 8 + gq_g];
#pragma unroll
        for (int mt = 0; mt < 4; mt++) {
            uint2 afl = Wc[(mt * 16 + gq_g) * PW1 + srow];
            uint2 afh = Wc[(mt * 16 + gq_g + 8) * PW1 + srow];
            mma_bf16(OC[mt][0], afl.x, afh.x, afl.y, afh.y, bf0.x, bf0.y);
            mma_bf16(OC[mt][1], afl.x, afh.x, afl.y, afh.y, bf1.x, bf1.y);
        }
    }

    // ---- step 4: BN1 + ReLU + pack n-pairs -> g_V64 ----
    {
        unsigned* vp32 = (unsigned*)g_V64;
        int t = (wid & 3) * 4 + gq_q;
        int ch = 2 * blockIdx.x + (wid >> 2);
#pragma unroll
        for (int mt = 0; mt < 4; mt++) {
            int d0 = mt * 16 + gq_g;
            float i0v = s_inv[d0], sh0 = s_shift[d0];
            float i1v = s_inv[d0 + 8], sh1 = s_shift[d0 + 8];
#pragma unroll
            for (int nt = 0; nt < 2; nt++) {
                float v00 = fmaxf(OC[mt][nt][0] * i0v + sh0, 0.f);
                float v01 = fmaxf(OC[mt][nt][1] * i0v + sh0, 0.f);
                float v10 = fmaxf(OC[mt][nt][2] * i1v + sh1, 0.f);
                float v11 = fmaxf(OC[mt][nt][3] * i1v + sh1, 0.f);
                size_t base0 = ((((size_t)b * 64 + d0) * 64 + ch) * 16 + t) * 2 + nt;
                size_t base1 = ((((size_t)b * 64 + d0 + 8) * 64 + ch) * 16 + t) * 2 + nt;
                vp32[base0] = packbf16(v00, v01);
                vp32[base1] = packbf16(v10, v11);
            }
        }
    }
}

// ---------------------------------------------------------------------------
// flash attention, bf16 m16n8k16, no-max softmax, Q in regs.
// SOFTWARE PIPELINE: PV lags one chunk -> exp(m) (MUFU) overlaps PV(m-1)
// (HMMA). V triple-buffered; K double-buffered; single PH array (WAR-safe:
// mma reads regs at issue, exp(m) overwrites after PV(m-1) issued).
// ---------------------------------------------------------------------------
__global__ __launch_bounds__(256) void attn_mma_kernel(const float* __restrict__ x)
{
    __shared__ __align__(16) unsigned long long Ks64[2][16 * PK64];
    __shared__ __align__(16) unsigned long long Vs64[3][64 * PV64];

    const int tid  = threadIdx.x;
    const int lane = tid & 31;
    const int wid  = tid >> 5;
    const int g    = lane >> 2;       // 0..7
    const int q    = lane & 3;        // 0..3
    const int i0   = wid * 32;

    const int b  = blockIdx.y;
    const int n0 = blockIdx.x * TNQ;
    const float* xb = x + (size_t)b * C * NSP;
    const unsigned long long* kb64 = g_K64 + (size_t)b * 16 * NSP;
    const unsigned long long* vb64 = g_V64 + (size_t)b * 64 * 64 * 16;

    unsigned ksa[2], vsa[3];
    ksa[0] = (unsigned)__cvta_generic_to_shared(&Ks64[0][0]);
    ksa[1] = (unsigned)__cvta_generic_to_shared(&Ks64[1][0]);
    vsa[0] = (unsigned)__cvta_generic_to_shared(&Vs64[0][0]);
    vsa[1] = (unsigned)__cvta_generic_to_shared(&Vs64[1][0]);
    vsa[2] = (unsigned)__cvta_generic_to_shared(&Vs64[2][0]);
    const int i2  = tid * 2;
    const int i2b = i2 + 512;

    // ---- Q A-fragments straight into registers (scale folded) ----
    unsigned QA[4][2][4];
#pragma unroll
    for (int ks = 0; ks < 4; ks++) {
#pragma unroll
        for (int rb = 0; rb < 2; rb++) {
            int re = n0 + i0 + rb * 16 + g;
            int d0 = 16 * ks + 2 * q;
            QA[ks][rb][0] = packbf16(xb[(size_t)d0 * NSP + re] * QSCALE,
                                     xb[(size_t)(d0 + 1) * NSP + re] * QSCALE);
            QA[ks][rb][1] = packbf16(xb[(size_t)d0 * NSP + re + 8] * QSCALE,
                                     xb[(size_t)(d0 + 1) * NSP + re + 8] * QSCALE);
            QA[ks][rb][2] = packbf16(xb[(size_t)(d0 + 8) * NSP + re] * QSCALE,
                                     xb[(size_t)(d0 + 9) * NSP + re] * QSCALE);
            QA[ks][rb][3] = packbf16(xb[(size_t)(d0 + 8) * NSP + re + 8] * QSCALE,
                                     xb[(size_t)(d0 + 9) * NSP + re + 8] * QSCALE);
        }
    }

    float SC[2][8][4];
    float OC[2][8][4];
    unsigned PH[2][8][2];             // P of the PREVIOUS chunk (single buffer)
#pragma unroll
    for (int rb = 0; rb < 2; rb++)
#pragma unroll
        for (int t = 0; t < 8; t++)
            OC[rb][t][0] = OC[rb][t][1] = OC[rb][t][2] = OC[rb][t][3] = 0.f;
    float rl[2][2] = {{0.f, 0.f}, {0.f, 0.f}};

    // issue K chunk -> kbuf, V chunk -> vbuf (each thread: 2 K + 2 V copies)
    #define ISSUE_CHUNK(m0, kbuf, vbuf) do {                                            \
        int _ch = (m0) >> 6;                                                            \
        cpa16(ksa[kbuf] + ((i2  >> 6) * PK64 + (i2  & 63)) * 8,                         \
              kb64 + (size_t)(i2  >> 6) * NSP + (m0) + (i2  & 63));                     \
        cpa16(ksa[kbuf] + ((i2b >> 6) * PK64 + (i2b & 63)) * 8,                         \
              kb64 + (size_t)(i2b >> 6) * NSP + (m0) + (i2b & 63));                     \
        cpa16(vsa[vbuf] + ((i2  >> 4) * PV64 + (i2  & 15)) * 8,                         \
              vb64 + (size_t)((i2  >> 4) * 64 + _ch) * 16 + (i2  & 15));                \
        cpa16(vsa[vbuf] + ((i2b >> 4) * PV64 + (i2b & 15)) * 8,                         \
              vb64 + (size_t)((i2b >> 4) * 64 + _ch) * 16 + (i2b & 15));                \
        asm volatile("cp.async.commit_group;");                                         \
    } while (0)

    ISSUE_CHUNK(0, 0, 0);

    int vm1 = 2;                      // (mm-1) % 3, unused at mm=0
    int vnx = 1;                      // (mm+1) % 3

    for (int mm = 0; mm < NSP / TMK; mm++) {
        int kcur = mm & 1;
        if (mm + 1 < NSP / TMK) {
            ISSUE_CHUNK((mm + 1) * TMK, 1 - kcur, vnx);
            asm volatile("cp.async.wait_group 1;");
        } else {
            asm volatile("cp.async.wait_group 0;");
        }
        __syncthreads();

        const uint2* Kc = (const uint2*)&Ks64[kcur][0];
        const uint2* Vp = (const uint2*)((const unsigned long long*)Vs64 + vm1 * (64 * PV64));

        // ---- S = Q K^T  (chunk mm) ----
#pragma unroll
        for (int rb = 0; rb < 2; rb++)
#pragma unroll
            for (int t = 0; t < 8; t++)
                SC[rb][t][0] = SC[rb][t][1] = SC[rb][t][2] = SC[rb][t][3] = 0.f;
#pragma unroll
        for (int ks = 0; ks < 4; ks++) {
            int srow = (ks * 4 + q) * PK64;
#pragma unroll
            for (int nt = 0; nt < 8; nt++) {
                uint2 kf = Kc[srow + nt * 8 + g];
                mma_bf16(SC[0][nt], QA[ks][0][0], QA[ks][0][1], QA[ks][0][2], QA[ks][0][3], kf.x, kf.y);
                mma_bf16(SC[1][nt], QA[ks][1][0], QA[ks][1][1], QA[ks][1][2], QA[ks][1][3], kf.x, kf.y);
            }
        }

        // ---- per jt: PV(mm-1) mma (reads PH) THEN exp(mm) overwrites PH ----
#pragma unroll
        for (int jt = 0; jt < 4; jt++) {
            if (mm > 0) {
                unsigned aA0 = PH[0][2 * jt][0],     aA1 = PH[0][2 * jt][1];
                unsigned aA2 = PH[0][2 * jt + 1][0], aA3 = PH[0][2 * jt + 1][1];
                unsigned aB0 = PH[1][2 * jt][0],     aB1 = PH[1][2 * jt][1];
                unsigned aB2 = PH[1][2 * jt + 1][0], aB3 = PH[1][2 * jt + 1][1];
#pragma unroll
                for (int nt2 = 0; nt2 < 8; nt2++) {
                    uint2 vf = Vp[(nt2 * 8 + g) * PV64 + jt * 4 + q];
                    mma_bf16(OC[0][nt2], aA0, aA1, aA2, aA3, vf.x, vf.y);
                    mma_bf16(OC[1][nt2], aB0, aB1, aB2, aB3, vf.x, vf.y);
                }
            }
            // exp of S tiles 2jt, 2jt+1 (both row-blocks) -> PH
#pragma unroll
            for (int rb = 0; rb < 2; rb++) {
#pragma unroll
                for (int u = 0; u < 2; u++) {
                    int nt = 2 * jt + u;
                    float e0 = ex2(SC[rb][nt][0]);
                    float e1 = ex2(SC[rb][nt][1]);
                    float e2 = ex2(SC[rb][nt][2]);
                    float e3 = ex2(SC[rb][nt][3]);
                    rl[rb][0] += e0 + e1;
                    rl[rb][1] += e2 + e3;
                    PH[rb][nt][0] = packbf16(e0, e1);
                    PH[rb][nt][1] = packbf16(e2, e3);
                }
            }
        }

        vm1 = (vm1 == 2) ? 0 : vm1 + 1;
        vnx = (vnx == 2) ? 0 : vnx + 1;
    }

    // ---- epilogue: PV of the last chunk (63). vm1 == 63 % 3 == 0 here ----
    {
        const uint2* Vp = (const uint2*)((const unsigned long long*)Vs64 + vm1 * (64 * PV64));
#pragma unroll
        for (int jt = 0; jt < 4; jt++) {
            unsigned aA0 = PH[0][2 * jt][0],     aA1 = PH[0][2 * jt][1];
            unsigned aA2 = PH[0][2 * jt + 1][0], aA3 = PH[0][2 * jt + 1][1];
            unsigned aB0 = PH[1][2 * jt][0],     aB1 = PH[1][2 * jt][1];
            unsigned aB2 = PH[1][2 * jt + 1][0], aB3 = PH[1][2 * jt + 1][1];
#pragma unroll
            for (int nt2 = 0; nt2 < 8; nt2++) {
                uint2 vf = Vp[(nt2 * 8 + g) * PV64 + jt * 4 + q];
                mma_bf16(OC[0][nt2], aA0, aA1, aA2, aA3, vf.x, vf.y);
                mma_bf16(OC[1][nt2], aB0, aB1, aB2, aB3, vf.x, vf.y);
            }
        }
    }

    // ---- final row-sum reduction ----
#pragma unroll
    for (int rb = 0; rb < 2; rb++) {
        rl[rb][0] += __shfl_xor_sync(0xffffffffu, rl[rb][0], 1);
        rl[rb][0] += __shfl_xor_sync(0xffffffffu, rl[rb][0], 2);
        rl[rb][1] += __shfl_xor_sync(0xffffffffu, rl[rb][1], 1);
        rl[rb][1] += __shfl_xor_sync(0xffffffffu, rl[rb][1], 2);
    }

    // ---- normalize + write ----
#pragma unroll
    for (int rb = 0; rb < 2; rb++) {
        float inv0 = 1.f / rl[rb][0], inv1 = 1.f / rl[rb][1];
        float* ob = g_attn + (size_t)b * C * NSP + n0 + i0 + rb * 16 + g;
#pragma unroll
        for (int nt2 = 0; nt2 < 8; nt2++) {
            int d0 = nt2 * 8 + 2 * q;
            ob[(size_t)d0 * NSP]           = OC[rb][nt2][0] * inv0;
            ob[(size_t)(d0 + 1) * NSP]     = OC[rb][nt2][1] * inv0;
            ob[(size_t)d0 * NSP + 8]       = OC[rb][nt2][2] * inv1;
            ob[(size_t)(d0 + 1) * NSP + 8] = OC[rb][nt2][3] * inv1;
        }
    }
    #undef ISSUE_CHUNK
}

// ---------------------------------------------------------------------------
// fused tail: dw 3x3 + BN2 + ReLU -> smem; conv1x1 (w3) via tf32 mma + BN3 +
// residual. CTA = (image row y, batch b); 256 threads.
// ---------------------------------------------------------------------------
#define USP 72
#define WSP 68
__global__ __launch_bounds__(256) void tail_kernel(
    const float* __restrict__ w2,
    const float* __restrict__ g2, const float* __restrict__ b2,
    const float* __restrict__ m2, const float* __restrict__ v2,
    const float* __restrict__ w3,
    const float* __restrict__ g3, const float* __restrict__ b3,
    const float* __restrict__ m3, const float* __restrict__ v3,
    const float* __restrict__ x, float* __restrict__ out)
{
    __shared__ float ws[C * WSP];
    __shared__ float Us[C * USP];
    __shared__ float s_inv[C], s_shift[C];

    int tid = threadIdx.x;
    int lane = tid & 31;
    int wid = tid >> 5;
    int y = blockIdx.x;
    int b = blockIdx.y;

    for (int i = tid; i < C * C; i += 256) {
        int r = i >> 6, c = i & 63;
        ws[r * WSP + c] = w3[i];
    }
    if (tid < C) {
        float inv = g3[tid] * rsqrtf(v3[tid] + EPSBN);
        s_inv[tid] = inv;
        s_shift[tid] = b3[tid] - m3[tid] * inv;
    }

    // ---- phase 1: depthwise, warp-per-channel passes (coalesced) ----
    {
        int xx = lane * 2;
#pragma unroll
        for (int p = 0; p < 8; p++) {
            int c = wid * 8 + p;
            const float* ip = g_attn + ((size_t)(b * 64 + c) << 12);
            float a0 = 0.f, a1 = 0.f;
#pragma unroll
            for (int dy = -1; dy <= 1; dy++) {
                int yy = y + dy;
                if (yy < 0 || yy >= HW) continue;
                const float* rp = ip + yy * HW + xx;
                float2 mid = *(const float2*)rp;
                float lft = (xx > 0) ? rp[-1] : 0.f;
                float rgt = (xx + 2 < HW) ? rp[2] : 0.f;
                float c0 = w2[c * 9 + (dy + 1) * 3 + 0];
                float c1 = w2[c * 9 + (dy + 1) * 3 + 1];
                float c2 = w2[c * 9 + (dy + 1) * 3 + 2];
                a0 += c0 * lft   + c1 * mid.x + c2 * mid.y;
                a1 += c0 * mid.x + c1 * mid.y + c2 * rgt;
            }
            float inv = g2[c] * rsqrtf(v2[c] + EPSBN);
            float sh = b2[c] - m2[c] * inv;
            Us[c * USP + xx]     = fmaxf(a0 * inv + sh, 0.f);
            Us[c * USP + xx + 1] = fmaxf(a1 * inv + sh, 0.f);
        }
    }
    __syncthreads();

    // ---- phase 2: conv1x1 via tf32 mma + BN3 + residual ----
    {
        const int g = lane >> 2, q = lane & 3;
        float OC3[4][4];
#pragma unroll
        for (int mt = 0; mt < 4; mt++)
            OC3[mt][0] = OC3[mt][1] = OC3[mt][2] = OC3[mt][3] = 0.f;

#pragma unroll
        for (int ks = 0; ks < 8; ks++) {
            unsigned b0 = f2tf32(Us[(ks * 8 + q) * USP + wid * 8 + g]);
            unsigned b1 = f2tf32(Us[(ks * 8 + q + 4) * USP + wid * 8 + g]);
#pragma unroll
            for (int mt = 0; mt < 4; mt++) {
                unsigned a0 = f2tf32(ws[(mt * 16 + g) * WSP + ks * 8 + q]);
                unsigned a1 = f2tf32(ws[(mt * 16 + g + 8) * WSP + ks * 8 + q]);
                unsigned a2 = f2tf32(ws[(mt * 16 + g) * WSP + ks * 8 + q + 4]);
                unsigned a3 = f2tf32(ws[(mt * 16 + g + 8) * WSP + ks * 8 + q + 4]);
                mma_tf32(OC3[mt], a0, a1, a2, a3, b0, b1);
            }
        }

        int n = y * HW + wid * 8 + 2 * q;
        const float* xp = x + (size_t)b * C * NSP + n;
        float* op = out + (size_t)b * C * NSP + n;
#pragma unroll
        for (int mt = 0; mt < 4; mt++) {
            int o0 = mt * 16 + g;
            float i0v = s_inv[o0], sh0 = s_shift[o0];
            float i1v = s_inv[o0 + 8], sh1 = s_shift[o0 + 8];
            op[(size_t)o0 * NSP]           = OC3[mt][0] * i0v + sh0 + xp[(size_t)o0 * NSP];
            op[(size_t)o0 * NSP + 1]       = OC3[mt][1] * i0v + sh0 + xp[(size_t)o0 * NSP + 1];
            op[(size_t)(o0 + 8) * NSP]     = OC3[mt][2] * i1v + sh1 + xp[(size_t)(o0 + 8) * NSP];
            op[(size_t)(o0 + 8) * NSP + 1] = OC3[mt][3] * i1v + sh1 + xp[(size_t)(o0 + 8) * NSP + 1];
        }
    }
}

// ---------------------------------------------------------------------------
extern "C" void kernel_launch(void* const* d_in, const int* in_sizes, int n_in,
                              void* d_out, int out_size)
{
    const float* x    = (const float*)d_in[0];
    const float* w1   = (const float*)d_in[1];
    const float* bn1g = (const float*)d_in[2];
    const float* bn1b = (const float*)d_in[3];
    const float* bn1m = (const float*)d_in[4];
    const float* bn1v = (const float*)d_in[5];
    const float* w2   = (const float*)d_in[6];
    const float* bn2g = (const float*)d_in[7];
    const float* bn2b = (const float*)d_in[8];
    const float* bn2m = (const float*)d_in[9];
    const float* bn2v = (const float*)d_in[10];
    const float* w3   = (const float*)d_in[11];
    const float* bn3g = (const float*)d_in[12];
    const float* bn3b = (const float*)d_in[13];
    const float* bn3m = (const float*)d_in[14];
    const float* bn3v = (const float*)d_in[15];
    float* out = (float*)d_out;

    conv1_mma_kernel<<<dim3(NSP / 128, BB), 256>>>(x, w1, bn1g, bn1b, bn1m, bn1v);
    attn_mma_kernel<<<dim3(NSP / TNQ, BB), 256>>>(x);
    tail_kernel<<<dim3(HW, BB), 256>>>(w2, bn2g, bn2b, bn2m, bn2v,
                                       w3, bn3g, bn3b, bn3m, bn3v, x, out);
}

// round 14
// speedup vs baseline: 1.2412x; 1.0208x over previous
#include <cuda_runtime.h>
#include <cuda_bf16.h>
#include <math.h>

#define C   64
#define HW  64
#define NSP 4096          // N = HW*HW spatial positions
#define BB  8             // batch
#define EPSBN 1e-5f

// attention tiling
#define TNQ 256           // query rows per CTA (8 warps x 32 rows)
#define TMK 64            // key/value chunk
#define PK64 68           // K smem pitch (u64): [16 slots][64 j]
#define PV64 20           // V smem pitch (u64): [64 d][16 slots]

// conv1 mma smem pitches
#define PB1 132
#define PW1 20

// scale: (1/8) * log2(e)
#define QSCALE 0.18033688f

// scratch (no allocations allowed -> device globals)
__device__ unsigned long long g_K64[BB * 16 * NSP];
__device__ unsigned long long g_V64[BB * 64 * 64 * 16];
__device__ float g_attn[BB * C * NSP];

// ---------------------------------------------------------------------------
// helpers
// ---------------------------------------------------------------------------
__device__ __forceinline__ unsigned packbf16(float lo, float hi) {
    unsigned r;
    asm("cvt.rn.bf16x2.f32 %0, %1, %2;" : "=r"(r) : "f"(hi), "f"(lo));
    return r;
}

__device__ __forceinline__ unsigned f2tf32(float f) {
    unsigned u;
    asm("cvt.rna.tf32.f32 %0, %1;" : "=r"(u) : "f"(f));
    return u;
}

__device__ __forceinline__ float ex2(float x) {
    float r;
    asm("ex2.approx.ftz.f32 %0, %1;" : "=f"(r) : "f"(x));
    return r;
}

__device__ __forceinline__ void mma_bf16(float c[4],
                                         unsigned a0, unsigned a1, unsigned a2, unsigned a3,
                                         unsigned b0, unsigned b1) {
    asm volatile(
        "mma.sync.aligned.m16n8k16.row.col.f32.bf16.bf16.f32 "
        "{%0,%1,%2,%3},{%4,%5,%6,%7},{%8,%9},{%0,%1,%2,%3};\n"
        : "+f"(c[0]), "+f"(c[1]), "+f"(c[2]), "+f"(c[3])
        : "r"(a0), "r"(a1), "r"(a2), "r"(a3), "r"(b0), "r"(b1));
}

__device__ __forceinline__ void mma_tf32(float c[4],
                                         unsigned a0, unsigned a1, unsigned a2, unsigned a3,
                                         unsigned b0, unsigned b1) {
    asm volatile(
        "mma.sync.aligned.m16n8k8.row.col.f32.tf32.tf32.f32 "
        "{%0,%1,%2,%3},{%4,%5,%6,%7},{%8,%9},{%0,%1,%2,%3};\n"
        : "+f"(c[0]), "+f"(c[1]), "+f"(c[2]), "+f"(c[3])
        : "r"(a0), "r"(a1), "r"(a2), "r"(a3), "r"(b0), "r"(b1));
}

__device__ __forceinline__ void cpa16(unsigned smem_addr, const void* gptr) {
    asm volatile("cp.async.cg.shared.global [%0], [%1], 16;"
                 :: "r"(smem_addr), "l"(gptr));
}

// ---------------------------------------------------------------------------
// conv1 via bf16 mma (unchanged from R12/R13)
// ---------------------------------------------------------------------------
__global__ __launch_bounds__(256) void conv1_mma_kernel(
    const float* __restrict__ x, const float* __restrict__ w1,
    const float* __restrict__ g, const float* __restrict__ bb,
    const float* __restrict__ m, const float* __restrict__ v)
{
    __shared__ __align__(16) unsigned long long Bs[16 * PB1];
    __shared__ __align__(16) unsigned long long Ws[64 * PW1];
    __shared__ float s_inv[C], s_shift[C];

    const int tid  = threadIdx.x;
    const int lane = tid & 31;
    const int wid  = tid >> 5;
    const int gq_g = lane >> 2;
    const int gq_q = lane & 3;

    const int b  = blockIdx.y;
    const int n0 = blockIdx.x * 128;
    const float* xb = x + (size_t)b * C * NSP;

    {
        unsigned long long* kp = g_K64 + (size_t)b * 16 * NSP;
#pragma unroll
        for (int i = 0; i < 8; i++) {
            int idx = tid + i * 256;
            int s = idx >> 7, n = idx & 127;
            int ks = s >> 2, q = s & 3;
            int c0 = 16 * ks + 2 * q;
            float xl0 = xb[(size_t)c0 * NSP + n0 + n];
            float xl1 = xb[(size_t)(c0 + 1) * NSP + n0 + n];
            float xh0 = xb[(size_t)(c0 + 8) * NSP + n0 + n];
            float xh1 = xb[(size_t)(c0 + 9) * NSP + n0 + n];
            unsigned lo = packbf16(xl0, xl1);
            unsigned hi = packbf16(xh0, xh1);
            unsigned long long u = (unsigned long long)lo | ((unsigned long long)hi << 32);
            Bs[s * PB1 + n] = u;
            kp[(size_t)s * NSP + n0 + n] = u;
        }
    }

    {
#pragma unroll
        for (int i = 0; i < 4; i++) {
            int idx = tid + i * 256;
            int r = idx >> 4, s = idx & 15;
            int ks = s >> 2, q = s & 3;
            const float* wr = w1 + r * 64 + 16 * ks + 2 * q;
            float2 wl = *(const float2*)wr;
            float2 wh = *(const float2*)(wr + 8);
            unsigned lo = packbf16(wl.x, wl.y);
            unsigned hi = packbf16(wh.x, wh.y);
            Ws[r * PW1 + s] = (unsigned long long)lo | ((unsigned long long)hi << 32);
        }
    }
    if (tid < C) {
        float inv = g[tid] * rsqrtf(v[tid] + EPSBN);
        s_inv[tid] = inv;
        s_shift[tid] = bb[tid] - m[tid] * inv;
    }
    __syncthreads();

    float OC[4][2][4];
#pragma unroll
    for (int mt = 0; mt < 4; mt++)
#pragma unroll
        for (int nt = 0; nt < 2; nt++)
            OC[mt][nt][0] = OC[mt][nt][1] = OC[mt][nt][2] = OC[mt][nt][3] = 0.f;

    const uint2* Bc = (const uint2*)Bs;
    const uint2* Wc = (const uint2*)Ws;
#pragma unroll
    for (int ks = 0; ks < 4; ks++) {
        int srow = (ks * 4 + gq_q);
        uint2 bf0 = Bc[srow * PB1 + wid * 16 + 0 * 8 + gq_g];
        uint2 bf1 = Bc[srow * PB1 + wid * 16 + 1 * 8 + gq_g];
#pragma unroll
        for (int mt = 0; mt < 4; mt++) {
            uint2 afl = Wc[(mt * 16 + gq_g) * PW1 + srow];
            uint2 afh = Wc[(mt * 16 + gq_g + 8) * PW1 + srow];
            mma_bf16(OC[mt][0], afl.x, afh.x, afl.y, afh.y, bf0.x, bf0.y);
            mma_bf16(OC[mt][1], afl.x, afh.x, afl.y, afh.y, bf1.x, bf1.y);
        }
    }

    {
        unsigned* vp32 = (unsigned*)g_V64;
        int t = (wid & 3) * 4 + gq_q;
        int ch = 2 * blockIdx.x + (wid >> 2);
#pragma unroll
        for (int mt = 0; mt < 4; mt++) {
            int d0 = mt * 16 + gq_g;
            float i0v = s_inv[d0], sh0 = s_shift[d0];
            float i1v = s_inv[d0 + 8], sh1 = s_shift[d0 + 8];
#pragma unroll
            for (int nt = 0; nt < 2; nt++) {
                float v00 = fmaxf(OC[mt][nt][0] * i0v + sh0, 0.f);
                float v01 = fmaxf(OC[mt][nt][1] * i0v + sh0, 0.f);
                float v10 = fmaxf(OC[mt][nt][2] * i1v + sh1, 0.f);
                float v11 = fmaxf(OC[mt][nt][3] * i1v + sh1, 0.f);
                size_t base0 = ((((size_t)b * 64 + d0) * 64 + ch) * 16 + t) * 2 + nt;
                size_t base1 = ((((size_t)b * 64 + d0 + 8) * 64 + ch) * 16 + t) * 2 + nt;
                vp32[base0] = packbf16(v00, v01);
                vp32[base1] = packbf16(v10, v11);
            }
        }
    }
}

// ---------------------------------------------------------------------------
// flash attention (R13 verbatim — PV lags one chunk, V triple-buffered)
// ---------------------------------------------------------------------------
__global__ __launch_bounds__(256) void attn_mma_kernel(const float* __restrict__ x)
{
    __shared__ __align__(16) unsigned long long Ks64[2][16 * PK64];
    __shared__ __align__(16) unsigned long long Vs64[3][64 * PV64];

    const int tid  = threadIdx.x;
    const int lane = tid & 31;
    const int wid  = tid >> 5;
    const int g    = lane >> 2;
    const int q    = lane & 3;
    const int i0   = wid * 32;

    const int b  = blockIdx.y;
    const int n0 = blockIdx.x * TNQ;
    const float* xb = x + (size_t)b * C * NSP;
    const unsigned long long* kb64 = g_K64 + (size_t)b * 16 * NSP;
    const unsigned long long* vb64 = g_V64 + (size_t)b * 64 * 64 * 16;

    unsigned ksa[2], vsa[3];
    ksa[0] = (unsigned)__cvta_generic_to_shared(&Ks64[0][0]);
    ksa[1] = (unsigned)__cvta_generic_to_shared(&Ks64[1][0]);
    vsa[0] = (unsigned)__cvta_generic_to_shared(&Vs64[0][0]);
    vsa[1] = (unsigned)__cvta_generic_to_shared(&Vs64[1][0]);
    vsa[2] = (unsigned)__cvta_generic_to_shared(&Vs64[2][0]);
    const int i2  = tid * 2;
    const int i2b = i2 + 512;

    unsigned QA[4][2][4];
#pragma unroll
    for (int ks = 0; ks < 4; ks++) {
#pragma unroll
        for (int rb = 0; rb < 2; rb++) {
            int re = n0 + i0 + rb * 16 + g;
            int d0 = 16 * ks + 2 * q;
            QA[ks][rb][0] = packbf16(xb[(size_t)d0 * NSP + re] * QSCALE,
                                     xb[(size_t)(d0 + 1) * NSP + re] * QSCALE);
            QA[ks][rb][1] = packbf16(xb[(size_t)d0 * NSP + re + 8] * QSCALE,
                                     xb[(size_t)(d0 + 1) * NSP + re + 8] * QSCALE);
            QA[ks][rb][2] = packbf16(xb[(size_t)(d0 + 8) * NSP + re] * QSCALE,
                                     xb[(size_t)(d0 + 9) * NSP + re] * QSCALE);
            QA[ks][rb][3] = packbf16(xb[(size_t)(d0 + 8) * NSP + re + 8] * QSCALE,
                                     xb[(size_t)(d0 + 9) * NSP + re + 8] * QSCALE);
        }
    }

    float SC[2][8][4];
    float OC[2][8][4];
    unsigned PH[2][8][2];
#pragma unroll
    for (int rb = 0; rb < 2; rb++)
#pragma unroll
        for (int t = 0; t < 8; t++)
            OC[rb][t][0] = OC[rb][t][1] = OC[rb][t][2] = OC[rb][t][3] = 0.f;
    float rl[2][2] = {{0.f, 0.f}, {0.f, 0.f}};

    #define ISSUE_CHUNK(m0, kbuf, vbuf) do {                                            \
        int _ch = (m0) >> 6;                                                            \
        cpa16(ksa[kbuf] + ((i2  >> 6) * PK64 + (i2  & 63)) * 8,                         \
              kb64 + (size_t)(i2  >> 6) * NSP + (m0) + (i2  & 63));                     \
        cpa16(ksa[kbuf] + ((i2b >> 6) * PK64 + (i2b & 63)) * 8,                         \
              kb64 + (size_t)(i2b >> 6) * NSP + (m0) + (i2b & 63));                     \
        cpa16(vsa[vbuf] + ((i2  >> 4) * PV64 + (i2  & 15)) * 8,                         \
              vb64 + (size_t)((i2  >> 4) * 64 + _ch) * 16 + (i2  & 15));                \
        cpa16(vsa[vbuf] + ((i2b >> 4) * PV64 + (i2b & 15)) * 8,                         \
              vb64 + (size_t)((i2b >> 4) * 64 + _ch) * 16 + (i2b & 15));                \
        asm volatile("cp.async.commit_group;");                                         \
    } while (0)

    ISSUE_CHUNK(0, 0, 0);

    int vm1 = 2;
    int vnx = 1;

    for (int mm = 0; mm < NSP / TMK; mm++) {
        int kcur = mm & 1;
        if (mm + 1 < NSP / TMK) {
            ISSUE_CHUNK((mm + 1) * TMK, 1 - kcur, vnx);
            asm volatile("cp.async.wait_group 1;");
        } else {
            asm volatile("cp.async.wait_group 0;");
        }
        __syncthreads();

        const uint2* Kc = (const uint2*)&Ks64[kcur][0];
        const uint2* Vp = (const uint2*)((const unsigned long long*)Vs64 + vm1 * (64 * PV64));

#pragma unroll
        for (int rb = 0; rb < 2; rb++)
#pragma unroll
            for (int t = 0; t < 8; t++)
                SC[rb][t][0] = SC[rb][t][1] = SC[rb][t][2] = SC[rb][t][3] = 0.f;
#pragma unroll
        for (int ks = 0; ks < 4; ks++) {
            int srow = (ks * 4 + q) * PK64;
#pragma unroll
            for (int nt = 0; nt < 8; nt++) {
                uint2 kf = Kc[srow + nt * 8 + g];
                mma_bf16(SC[0][nt], QA[ks][0][0], QA[ks][0][1], QA[ks][0][2], QA[ks][0][3], kf.x, kf.y);
                mma_bf16(SC[1][nt], QA[ks][1][0], QA[ks][1][1], QA[ks][1][2], QA[ks][1][3], kf.x, kf.y);
            }
        }

#pragma unroll
        for (int jt = 0; jt < 4; jt++) {
            if (mm > 0) {
                unsigned aA0 = PH[0][2 * jt][0],     aA1 = PH[0][2 * jt][1];
                unsigned aA2 = PH[0][2 * jt + 1][0], aA3 = PH[0][2 * jt + 1][1];
                unsigned aB0 = PH[1][2 * jt][0],     aB1 = PH[1][2 * jt][1];
                unsigned aB2 = PH[1][2 * jt + 1][0], aB3 = PH[1][2 * jt + 1][1];
#pragma unroll
                for (int nt2 = 0; nt2 < 8; nt2++) {
                    uint2 vf = Vp[(nt2 * 8 + g) * PV64 + jt * 4 + q];
                    mma_bf16(OC[0][nt2], aA0, aA1, aA2, aA3, vf.x, vf.y);
                    mma_bf16(OC[1][nt2], aB0, aB1, aB2, aB3, vf.x, vf.y);
                }
            }
#pragma unroll
            for (int rb = 0; rb < 2; rb++) {
#pragma unroll
                for (int u = 0; u < 2; u++) {
                    int nt = 2 * jt + u;
                    float e0 = ex2(SC[rb][nt][0]);
                    float e1 = ex2(SC[rb][nt][1]);
                    float e2 = ex2(SC[rb][nt][2]);
                    float e3 = ex2(SC[rb][nt][3]);
                    rl[rb][0] += e0 + e1;
                    rl[rb][1] += e2 + e3;
                    PH[rb][nt][0] = packbf16(e0, e1);
                    PH[rb][nt][1] = packbf16(e2, e3);
                }
            }
        }

        vm1 = (vm1 == 2) ? 0 : vm1 + 1;
        vnx = (vnx == 2) ? 0 : vnx + 1;
    }

    {
        const uint2* Vp = (const uint2*)((const unsigned long long*)Vs64 + vm1 * (64 * PV64));
#pragma unroll
        for (int jt = 0; jt < 4; jt++) {
            unsigned aA0 = PH[0][2 * jt][0],     aA1 = PH[0][2 * jt][1];
            unsigned aA2 = PH[0][2 * jt + 1][0], aA3 = PH[0][2 * jt + 1][1];
            unsigned aB0 = PH[1][2 * jt][0],     aB1 = PH[1][2 * jt][1];
            unsigned aB2 = PH[1][2 * jt + 1][0], aB3 = PH[1][2 * jt + 1][1];
#pragma unroll
            for (int nt2 = 0; nt2 < 8; nt2++) {
                uint2 vf = Vp[(nt2 * 8 + g) * PV64 + jt * 4 + q];
                mma_bf16(OC[0][nt2], aA0, aA1, aA2, aA3, vf.x, vf.y);
                mma_bf16(OC[1][nt2], aB0, aB1, aB2, aB3, vf.x, vf.y);
            }
        }
    }

#pragma unroll
    for (int rb = 0; rb < 2; rb++) {
        rl[rb][0] += __shfl_xor_sync(0xffffffffu, rl[rb][0], 1);
        rl[rb][0] += __shfl_xor_sync(0xffffffffu, rl[rb][0], 2);
        rl[rb][1] += __shfl_xor_sync(0xffffffffu, rl[rb][1], 1);
        rl[rb][1] += __shfl_xor_sync(0xffffffffu, rl[rb][1], 2);
    }

#pragma unroll
    for (int rb = 0; rb < 2; rb++) {
        float inv0 = 1.f / rl[rb][0], inv1 = 1.f / rl[rb][1];
        float* ob = g_attn + (size_t)b * C * NSP + n0 + i0 + rb * 16 + g;
#pragma unroll
        for (int nt2 = 0; nt2 < 8; nt2++) {
            int d0 = nt2 * 8 + 2 * q;
            ob[(size_t)d0 * NSP]           = OC[rb][nt2][0] * inv0;
            ob[(size_t)(d0 + 1) * NSP]     = OC[rb][nt2][1] * inv0;
            ob[(size_t)d0 * NSP + 8]       = OC[rb][nt2][2] * inv1;
            ob[(size_t)(d0 + 1) * NSP + 8] = OC[rb][nt2][3] * inv1;
        }
    }
    #undef ISSUE_CHUNK
}

// ---------------------------------------------------------------------------
// fused tail, 2 image rows per CTA: dw 3x3 + BN2 + ReLU -> smem (tf32 bits);
// conv1x1 (w3) via tf32 mma + BN3 + residual. Dynamic smem.
// grid (HW/2, BB); 256 threads.
// ---------------------------------------------------------------------------
#define WSP 68
#define UPR 72            // per-row pitch within a channel
#define UPC 152           // per-channel pitch (2*UPR + 8); 152 mod 32 = 24
__global__ __launch_bounds__(256) void tail_kernel(
    const float* __restrict__ w2,
    const float* __restrict__ g2, const float* __restrict__ b2,
    const float* __restrict__ m2, const float* __restrict__ v2,
    const float* __restrict__ w3,
    const float* __restrict__ g3, const float* __restrict__ b3,
    const float* __restrict__ m3, const float* __restrict__ v3,
    const float* __restrict__ x, float* __restrict__ out)
{
    extern __shared__ float smem_f[];
    float* ws = smem_f;                     // [64 * WSP] tf32 bits
    float* Us = ws + C * WSP;               // [64 * UPC] tf32 bits
    float* s_inv = Us + C * UPC;            // [64]
    float* s_shift = s_inv + C;             // [64]

    int tid = threadIdx.x;
    int lane = tid & 31;
    int wid = tid >> 5;
    int y0 = blockIdx.x * 2;
    int b = blockIdx.y;

    for (int i = tid; i < C * C; i += 256) {
        int r = i >> 6, c = i & 63;
        ws[r * WSP + c] = __uint_as_float(f2tf32(w3[i]));
    }
    if (tid < C) {
        float inv = g3[tid] * rsqrtf(v3[tid] + EPSBN);
        s_inv[tid] = inv;
        s_shift[tid] = b3[tid] - m3[tid] * inv;
    }

    // ---- phase 1: depthwise for rows y0, y0+1; 4 halo rows loaded once ----
    {
        int xx = lane * 2;
#pragma unroll
        for (int p = 0; p < 8; p++) {
            int c = wid * 8 + p;
            const float* ip = g_attn + ((size_t)(b * 64 + c) << 12);

            float lf[4], m0[4], m1[4], rg[4];
#pragma unroll
            for (int i = 0; i < 4; i++) {
                int yy = y0 - 1 + i;
                if (yy >= 0 && yy < HW) {
                    const float* rp = ip + yy * HW + xx;
                    float2 mid = *(const float2*)rp;
                    lf[i] = (xx > 0) ? rp[-1] : 0.f;
                    m0[i] = mid.x; m1[i] = mid.y;
                    rg[i] = (xx + 2 < HW) ? rp[2] : 0.f;
                } else {
                    lf[i] = m0[i] = m1[i] = rg[i] = 0.f;
                }
            }

            float inv = g2[c] * rsqrtf(v2[c] + EPSBN);
            float sh = b2[c] - m2[c] * inv;
#pragma unroll
            for (int r = 0; r < 2; r++) {
                float a0 = 0.f, a1 = 0.f;
#pragma unroll
                for (int dy = 0; dy < 3; dy++) {
                    int i = r + dy;
                    float c0 = w2[c * 9 + dy * 3 + 0];
                    float c1 = w2[c * 9 + dy * 3 + 1];
                    float c2 = w2[c * 9 + dy * 3 + 2];
                    a0 += c0 * lf[i] + c1 * m0[i] + c2 * m1[i];
                    a1 += c0 * m0[i] + c1 * m1[i] + c2 * rg[i];
                }
                float u0 = fmaxf(a0 * inv + sh, 0.f);
                float u1 = fmaxf(a1 * inv + sh, 0.f);
                Us[c * UPC + r * UPR + xx]     = __uint_as_float(f2tf32(u0));
                Us[c * UPC + r * UPR + xx + 1] = __uint_as_float(f2tf32(u1));
            }
        }
    }
    __syncthreads();

    // ---- phase 2: conv1x1 via tf32 mma + BN3 + residual, per output row ----
    {
        const int g = lane >> 2, q = lane & 3;
#pragma unroll
        for (int r = 0; r < 2; r++) {
            const float* Ur = Us + r * UPR;
            float OC3[4][4];
#pragma unroll
            for (int mt = 0; mt < 4; mt++)
                OC3[mt][0] = OC3[mt][1] = OC3[mt][2] = OC3[mt][3] = 0.f;

#pragma unroll
            for (int ks = 0; ks < 8; ks++) {
                unsigned b0 = __float_as_uint(Ur[(ks * 8 + q) * UPC + wid * 8 + g]);
                unsigned b1 = __float_as_uint(Ur[(ks * 8 + q + 4) * UPC + wid * 8 + g]);
#pragma unroll
                for (int mt = 0; mt < 4; mt++) {
                    unsigned a0 = __float_as_uint(ws[(mt * 16 + g) * WSP + ks * 8 + q]);
                    unsigned a1 = __float_as_uint(ws[(mt * 16 + g + 8) * WSP + ks * 8 + q]);
                    unsigned a2 = __float_as_uint(ws[(mt * 16 + g) * WSP + ks * 8 + q + 4]);
                    unsigned a3 = __float_as_uint(ws[(mt * 16 + g + 8) * WSP + ks * 8 + q + 4]);
                    mma_tf32(OC3[mt], a0, a1, a2, a3, b0, b1);
                }
            }

            int n = (y0 + r) * HW + wid * 8 + 2 * q;
            const float* xp = x + (size_t)b * C * NSP + n;
            float* op = out + (size_t)b * C * NSP + n;
#pragma unroll
            for (int mt = 0; mt < 4; mt++) {
                int o0 = mt * 16 + g;
                float i0v = s_inv[o0], sh0 = s_shift[o0];
                float i1v = s_inv[o0 + 8], sh1 = s_shift[o0 + 8];
                op[(size_t)o0 * NSP]           = OC3[mt][0] * i0v + sh0 + xp[(size_t)o0 * NSP];
                op[(size_t)o0 * NSP + 1]       = OC3[mt][1] * i0v + sh0 + xp[(size_t)o0 * NSP + 1];
                op[(size_t)(o0 + 8) * NSP]     = OC3[mt][2] * i1v + sh1 + xp[(size_t)(o0 + 8) * NSP];
                op[(size_t)(o0 + 8) * NSP + 1] = OC3[mt][3] * i1v + sh1 + xp[(size_t)(o0 + 8) * NSP + 1];
            }
        }
    }
}

// ---------------------------------------------------------------------------
extern "C" void kernel_launch(void* const* d_in, const int* in_sizes, int n_in,
                              void* d_out, int out_size)
{
    const float* x    = (const float*)d_in[0];
    const float* w1   = (const float*)d_in[1];
    const float* bn1g = (const float*)d_in[2];
    const float* bn1b = (const float*)d_in[3];
    const float* bn1m = (const float*)d_in[4];
    const float* bn1v = (const float*)d_in[5];
    const float* w2   = (const float*)d_in[6];
    const float* bn2g = (const float*)d_in[7];
    const float* bn2b = (const float*)d_in[8];
    const float* bn2m = (const float*)d_in[9];
    const float* bn2v = (const float*)d_in[10];
    const float* w3   = (const float*)d_in[11];
    const float* bn3g = (const float*)d_in[12];
    const float* bn3b = (const float*)d_in[13];
    const float* bn3m = (const float*)d_in[14];
    const float* bn3v = (const float*)d_in[15];
    float* out = (float*)d_out;

    const int tail_smem = (C * WSP + C * UPC + 2 * C) * 4;   // ~56.9 KB
    cudaFuncSetAttribute(tail_kernel,
                         cudaFuncAttributeMaxDynamicSharedMemorySize, tail_smem);

    conv1_mma_kernel<<<dim3(NSP / 128, BB), 256>>>(x, w1, bn1g, bn1b, bn1m, bn1v);
    attn_mma_kernel<<<dim3(NSP / TNQ, BB), 256>>>(x);
    tail_kernel<<<dim3(HW / 2, BB), 256, tail_smem>>>(w2, bn2g, bn2b, bn2m, bn2v,
                                                      w3, bn3g, bn3b, bn3m, bn3v, x, out);
}